// round 11
// baseline (speedup 1.0000x reference)
#include <cuda_runtime.h>
#include <cuda_fp16.h>
#include <math_constants.h>
#include <cstdint>

// Problem constants (fixed shapes)
#define NN 100000
#define EE 800000
#define WC 768   // fused weight cols: [q 128][k 128][v 128][skip 128][p0 96][p1 96][pad 64]

// ------------------------- device scratch -------------------------
__device__ __half g_dst[(size_t)NN * 320];           // per-node dst data: q[128], p[192] fp16
__device__ __half g_src[(size_t)NN * 256];           // per-node src data: k[128], v[128] fp16
__device__ __half g_whT[WC * 128];                   // W^T (fp16), [col][k]
__device__ float g_bias[WC];
// sort scratch (SoA sorted edge data)
__device__ int g_cnt[NN];
__device__ int g_off[NN + 1];
__device__ int g_cursor[NN];
__device__ int2 g_edat[EE];                          // sorted {src, rel_t bits}
__device__ int g_eidx[EE];
__device__ __half g_emsg[(size_t)EE * 64];           // sorted msg, fp16
__device__ int g_bsum[512];

// ------------------------- generic helpers -------------------------
__device__ __forceinline__ unsigned long long pk2(float lo, float hi) {
    unsigned long long r;
    asm("mov.b64 %0, {%1,%2};" : "=l"(r) : "f"(lo), "f"(hi));
    return r;
}
__device__ __forceinline__ float2 upk2(unsigned long long v) {
    float2 r;
    asm("mov.b64 {%0,%1}, %2;" : "=f"(r.x), "=f"(r.y) : "l"(v));
    return r;
}
__device__ __forceinline__ unsigned long long ffma2(unsigned long long a, unsigned long long b,
                                                    unsigned long long c) {
    unsigned long long d;
    asm("fma.rn.f32x2 %0, %1, %2, %3;" : "=l"(d) : "l"(a), "l"(b), "l"(c));
    return d;
}
__device__ __forceinline__ uint32_t smem_u32(const void* p) {
    uint32_t a;
    asm("{ .reg .u64 t; cvta.to.shared.u64 t, %1; cvt.u32.u64 %0, t; }" : "=r"(a) : "l"(p));
    return a;
}
__device__ __forceinline__ void ldsm4(uint32_t* r, uint32_t addr) {
    asm volatile("ldmatrix.sync.aligned.m8n8.x4.shared.b16 {%0,%1,%2,%3}, [%4];"
                 : "=r"(r[0]), "=r"(r[1]), "=r"(r[2]), "=r"(r[3]) : "r"(addr));
}
__device__ __forceinline__ void mma16816(float* c, const uint32_t* a, uint32_t b0, uint32_t b1) {
    asm volatile(
        "mma.sync.aligned.m16n8k16.row.col.f32.f16.f16.f32 "
        "{%0,%1,%2,%3}, {%4,%5,%6,%7}, {%8,%9}, {%0,%1,%2,%3};"
        : "+f"(c[0]), "+f"(c[1]), "+f"(c[2]), "+f"(c[3])
        : "r"(a[0]), "r"(a[1]), "r"(a[2]), "r"(a[3]), "r"(b0), "r"(b1));
}
__device__ __forceinline__ void cp16(uint32_t saddr, const void* g) {
    asm volatile("cp.async.cg.shared.global [%0], [%1], 16;" :: "r"(saddr), "l"(g));
}
#define CP_COMMIT() asm volatile("cp.async.commit_group;" ::: "memory")
#define CP_WAIT1()  asm volatile("cp.async.wait_group 1;" ::: "memory")
#define CP_WAIT0()  asm volatile("cp.async.wait_group 0;" ::: "memory")

// ------------------------- kernel: init sort scratch -------------------------
__global__ void k_init() {
    int i = blockIdx.x * blockDim.x + threadIdx.x;
    if (i < NN) {
        g_cnt[i] = 0;
        g_cursor[i] = 0;
    }
}

// ------------------------- kernel: fused weights (transposed, fp16) ----------
__global__ void k_prep(const float* __restrict__ Wq, const float* __restrict__ bq,
                       const float* __restrict__ Wk, const float* __restrict__ bk,
                       const float* __restrict__ Wv, const float* __restrict__ bv,
                       const float* __restrict__ We,
                       const float* __restrict__ Ws, const float* __restrict__ bs) {
    int i = blockIdx.x;  // 0..127 (input dim k)
    for (int c = threadIdx.x; c < WC; c += blockDim.x) {
        float w = 0.0f, b = 0.0f;
        if (c < 128)      { w = Wq[i * 128 + c];         b = bq[c]; }
        else if (c < 256) { w = Wk[i * 128 + (c - 128)]; b = bk[c - 128]; }
        else if (c < 384) { w = Wv[i * 128 + (c - 256)]; b = bv[c - 256]; }
        else if (c < 512) { w = Ws[i * 128 + (c - 384)]; b = bs[c - 384]; }
        else if (c < 704) {
            int hd = c - 512;
            int h = hd / 96, d = hd % 96;
            float acc = 0.0f, accb = 0.0f;
            #pragma unroll 8
            for (int cc = 0; cc < 64; ++cc) {
                float we = We[d * 128 + h * 64 + cc];
                acc = fmaf(Wq[i * 128 + h * 64 + cc], we, acc);
                accb = fmaf(bq[h * 64 + cc], we, accb);
            }
            w = acc; b = accb;
        }
        g_whT[c * 128 + i] = __float2half_rn(w);
        if (i == 0) g_bias[c] = b;
    }
}

// ------------------------- kernel: HMMA node GEMM (fp16 single-term) ---------
#define A_ROWS 64
#define A_STRIDE 136
#define B_STRIDE 72
#define SZ_A (A_ROWS * A_STRIDE * 2)      // 17408 (single fp16 A)
#define SZ_B (128 * B_STRIDE * 2)         // 18432 per buffer
#define SM_A    0
#define SM_B    (SZ_A)                    // 2 buffers
#define SM_BIAS (SZ_A + 2 * SZ_B)         // 54272
#define SM_TOT  (SM_BIAS + WC * 4)        // 57344

__device__ __forceinline__ void load_B_async(uint32_t sb, int s, int tid) {
    const int chunk = s >> 1, kh = s & 1;
    const uint32_t bbase = SM_B + (uint32_t)(s & 1) * SZ_B;
    for (int i = tid; i < 128 * 8; i += 256) {
        int c = i >> 3, seg = i & 7;
        size_t gsrc = (size_t)(chunk * 128 + c) * 128 + kh * 64 + seg * 8;
        uint32_t doff = (uint32_t)(c * (B_STRIDE * 2) + seg * 16);
        cp16(sb + bbase + doff, g_whT + gsrc);
    }
}

__global__ void __launch_bounds__(256, 3) k_gemm_mma(const float* __restrict__ x,
                                                     float* __restrict__ out) {
    extern __shared__ char smem[];
    const uint32_t sb = smem_u32(smem);
    const int tid = threadIdx.x, wid = tid >> 5, lane = tid & 31;
    const int row0 = blockIdx.x * A_ROWS;

    load_B_async(sb, 0, tid);
    CP_COMMIT();

    float* sbias = (float*)(smem + SM_BIAS);
    for (int i = tid; i < WC; i += 256) sbias[i] = g_bias[i];

    // load A tile [64x128] as single fp16
    for (int i = tid; i < A_ROWS * 32; i += 256) {
        int r = i >> 5, k4 = (i & 31) << 2;
        int row = row0 + r;
        float4 v = (row < NN) ? __ldcs((const float4*)(x + (size_t)row * 128 + k4))
                              : make_float4(0.f, 0.f, 0.f, 0.f);
        __half2 h01 = __floats2half2_rn(v.x, v.y);
        __half2 h23 = __floats2half2_rn(v.z, v.w);
        uint32_t off = (uint32_t)(r * (A_STRIDE * 2) + k4 * 2);
        *(uint2*)(smem + SM_A + off) = make_uint2(*(uint32_t*)&h01, *(uint32_t*)&h23);
    }

    const int wm = wid & 1, wn = wid >> 1;       // warp grid 2 x 4
    const int rw = wm * 32, cw = wn * 32;        // warp tile 32 x 32
    const uint32_t a_off = (uint32_t)((rw + (lane & 15)) * (A_STRIDE * 2) + (lane >> 4) * 16);
    const uint32_t b_off = (uint32_t)((cw + (lane & 15)) * (B_STRIDE * 2) + (lane >> 4) * 16);
    const int trow = lane >> 2;
    const int tcol = (lane & 3) * 2;

    float acc[2][4][4];

    for (int s = 0; s < 12; ++s) {
        const int chunk = s >> 1, kh = s & 1;
        if (kh == 0) {
            #pragma unroll
            for (int i = 0; i < 2; ++i)
                #pragma unroll
                for (int j = 0; j < 4; ++j)
                    #pragma unroll
                    for (int q = 0; q < 4; ++q) acc[i][j][q] = 0.0f;
        }
        if (s + 1 < 12) {
            load_B_async(sb, s + 1, tid);
            CP_COMMIT();
            CP_WAIT1();
        } else {
            CP_WAIT0();
        }
        __syncthreads();

        const uint32_t sA = sb + SM_A + kh * 128;
        const uint32_t sBh = sb + SM_B + (uint32_t)(s & 1) * SZ_B;
        #pragma unroll
        for (int ks = 0; ks < 4; ++ks) {
            uint32_t a[2][4], bh[2][4];
            #pragma unroll
            for (int i = 0; i < 2; ++i)
                ldsm4(a[i], sA + a_off + i * (16 * A_STRIDE * 2) + ks * 32);
            #pragma unroll
            for (int j16 = 0; j16 < 2; ++j16)
                ldsm4(bh[j16], sBh + b_off + j16 * (16 * B_STRIDE * 2) + ks * 32);
            #pragma unroll
            for (int i = 0; i < 2; ++i) {
                mma16816(acc[i][0], a[i], bh[0][0], bh[0][2]);
                mma16816(acc[i][1], a[i], bh[0][1], bh[0][3]);
                mma16816(acc[i][2], a[i], bh[1][0], bh[1][2]);
                mma16816(acc[i][3], a[i], bh[1][1], bh[1][3]);
            }
        }
        __syncthreads();

        if (kh == 1) {
            if (chunk == 3) {
                // skip -> out (fp32)
                #pragma unroll
                for (int i = 0; i < 2; ++i) {
                    int r = row0 + rw + i * 16 + trow;
                    #pragma unroll
                    for (int j = 0; j < 4; ++j) {
                        int G = 384 + cw + j * 8 + tcol;
                        float b0 = sbias[G], b1 = sbias[G + 1];
                        if (r < NN) {
                            float2 v = make_float2(acc[i][j][0] + b0, acc[i][j][1] + b1);
                            __stcs((float2*)(out + (size_t)r * 128 + (G - 384)), v);
                        }
                        if (r + 8 < NN) {
                            float2 v = make_float2(acc[i][j][2] + b0, acc[i][j][3] + b1);
                            __stcs((float2*)(out + (size_t)(r + 8) * 128 + (G - 384)), v);
                        }
                    }
                }
            } else {
                // q/p -> g_dst fp16, k/v -> g_src fp16
                __half* bp; int stride, sub;
                bool is_kv = (chunk == 1 || chunk == 2);
                if (chunk == 0)      { bp = g_dst; stride = 320; sub = 0;   }
                else if (is_kv)      { bp = g_src; stride = 256; sub = 128; }
                else                 { bp = g_dst; stride = 320; sub = 384; }
                #pragma unroll
                for (int i = 0; i < 2; ++i) {
                    int r = row0 + rw + i * 16 + trow;
                    #pragma unroll
                    for (int j = 0; j < 4; ++j) {
                        int G = chunk * 128 + cw + j * 8 + tcol;
                        if (G >= 704) continue;
                        float b0 = sbias[G], b1 = sbias[G + 1];
                        if (r < NN) {
                            __half2 hv = __floats2half2_rn(acc[i][j][0] + b0,
                                                           acc[i][j][1] + b1);
                            *(__half2*)(bp + (size_t)r * stride + (G - sub)) = hv;
                        }
                        if (r + 8 < NN) {
                            __half2 hv = __floats2half2_rn(acc[i][j][2] + b0,
                                                           acc[i][j][3] + b1);
                            *(__half2*)(bp + (size_t)(r + 8) * stride + (G - sub)) = hv;
                        }
                    }
                }
            }
        }
    }
}

// ------------------------- sort: histogram, scan, permute -------------------------
__global__ void k_hist(const int* __restrict__ ei) {
    int i = blockIdx.x * blockDim.x + threadIdx.x;
    if (i < EE) atomicAdd(&g_cnt[__ldcs(ei + EE + i)], 1);
}

__global__ void k_scan_a() {
    __shared__ int sm[256];
    int t = threadIdx.x;
    int gid = blockIdx.x * 256 + t;
    int val = (gid < NN) ? g_cnt[gid] : 0;
    sm[t] = val;
    __syncthreads();
    #pragma unroll
    for (int o = 1; o < 256; o <<= 1) {
        int add = (t >= o) ? sm[t - o] : 0;
        __syncthreads();
        sm[t] += add;
        __syncthreads();
    }
    if (gid < NN) g_off[gid] = sm[t] - val;
    if (t == 255) g_bsum[blockIdx.x] = sm[255];
}

__global__ void k_scan_b(int nblk) {
    __shared__ int sm[512];
    int t = threadIdx.x;
    int val = (t < nblk) ? g_bsum[t] : 0;
    sm[t] = val;
    __syncthreads();
    #pragma unroll
    for (int o = 1; o < 512; o <<= 1) {
        int add = (t >= o) ? sm[t - o] : 0;
        __syncthreads();
        sm[t] += add;
        __syncthreads();
    }
    if (t < nblk) g_bsum[t] = sm[t] - val;
}

__global__ void k_scan_c() {
    int gid = blockIdx.x * 256 + threadIdx.x;
    if (gid < NN) g_off[gid] += g_bsum[blockIdx.x];
    if (gid == 0) g_off[NN] = EE;
}

__global__ void k_permute(const int* __restrict__ ei, const float* __restrict__ lu,
                          const float* __restrict__ tv) {
    int i = blockIdx.x * blockDim.x + threadIdx.x;
    if (i >= EE) return;
    int d = __ldcs(ei + EE + i);
    int s = __ldcs(ei + i);
    int pos = g_off[d] + atomicAdd(&g_cursor[d], 1);
    float rel = lu[s] - __ldcs(tv + i);
    g_edat[pos] = make_int2(s, __float_as_int(rel));
    g_eidx[pos] = i;
}

// permute msg into sorted order, fp16. Warp per edge.
__global__ void k_pmsg(const float* __restrict__ msg) {
    int pos = blockIdx.x * 8 + (threadIdx.x >> 5);
    int lane = threadIdx.x & 31;
    if (pos >= EE) return;
    int idx = __ldcs(g_eidx + pos);
    float2 m = __ldcs((const float2*)(msg + (size_t)idx * 64 + lane * 2));
    __half2 h = __floats2half2_rn(m.x, m.y);
    __stcs((unsigned*)(g_emsg + (size_t)pos * 64 + lane * 2), *(unsigned*)&h);
}

// ------------------------- kernel: fused edge pass + s@We epilogue -------------
// Persistent: 1480 CTAs, warp-per-node strided loop. We staged in smem per CTA.
#define EDGE_CTAS 1480
#define EDGE_WARPS (EDGE_CTAS * 8)
#define SM_EDGE ((96 * 128 + 8 * 192) * 4)   // We fp32 + per-warp s: 55296 B

__global__ void __launch_bounds__(256) k_edge(const float* __restrict__ time_w,
                                              const float* __restrict__ time_b,
                                              const float* __restrict__ We,
                                              float* __restrict__ out) {
    extern __shared__ float sme[];
    float* sWe = sme;                     // [96][128]
    const int tid = threadIdx.x, wid = tid >> 5, lane = tid & 31;

    for (int i = tid; i < 96 * 128 / 4; i += 256)
        ((float4*)sWe)[i] = ((const float4*)We)[i];
    __syncthreads();

    float* sS = sme + 96 * 128 + wid * 192;   // per-warp s[d][h]
    const float tww = time_w[lane], tbb = time_b[lane];
    const bool h0lane = (lane < 16);
    const int hsel = h0lane ? 0 : 1;
    const unsigned short* emsg = (const unsigned short*)g_emsg;

    for (int n = blockIdx.x * 8 + wid; n < NN; n += EDGE_WARPS) {
        const int off0 = g_off[n];
        const int deg = g_off[n + 1] - off0;
        if (deg == 0) continue;   // out already holds skip

        const __half* dp = g_dst + (size_t)n * 320;
        int2 qr = __ldcs((const int2*)(dp + lane * 4));
        float2 qa = __half22float2(*(const __half2*)&qr.x);
        float2 qb = __half22float2(*(const __half2*)&qr.y);
        const float4 q4 = make_float4(qa.x, qa.y, qb.x, qb.y);
        short ps0 = __ldcs((const short*)(dp + 128 + lane));
        short ps1 = __ldcs((const short*)(dp + 160 + lane));
        short ps2 = __ldcs((const short*)(dp + 192 + lane));
        short ps3 = __ldcs((const short*)(dp + 224 + lane));
        short ps4 = __ldcs((const short*)(dp + 256 + lane));
        short ps5 = __ldcs((const short*)(dp + 288 + lane));
        const float p00 = __half2float(*(__half*)&ps0), p01 = __half2float(*(__half*)&ps1);
        const float p02 = __half2float(*(__half*)&ps2), p10 = __half2float(*(__half*)&ps3);
        const float p11 = __half2float(*(__half*)&ps4), p12 = __half2float(*(__half*)&ps5);

        float den0 = 0.f, den1 = 0.f;
        float4 aco = make_float4(0.f, 0.f, 0.f, 0.f);
        float2 as0 = make_float2(0.f, 0.f), as1 = as0, as2 = as0;

        for (int eb = 0; eb < deg; eb += 4) {
            const int nb = deg - eb;
            int srcj[4];
            float relj[4], ea0[4], ea1[4], ea2[4], u0[4], u1[4];
            float4 k4[4], v4[4];
            #pragma unroll
            for (int j = 0; j < 4; ++j) {
                int pos = off0 + eb + ((j < nb) ? j : 0);
                int2 ed = __ldcs(g_edat + pos);
                srcj[j] = ed.x;
                relj[j] = __int_as_float(ed.y);
                unsigned short m1 = __ldcs(emsg + (size_t)pos * 64 + lane);
                unsigned short m2 = __ldcs(emsg + (size_t)pos * 64 + 32 + lane);
                ea1[j] = __half2float(*(__half*)&m1);
                ea2[j] = __half2float(*(__half*)&m2);
            }
            #pragma unroll
            for (int j = 0; j < 4; ++j) {
                const __half* sp = g_src + (size_t)srcj[j] * 256;
                uint2 kr = *(const uint2*)(sp + lane * 4);     // cached: reused ~8x
                uint2 vr = *(const uint2*)(sp + 128 + lane * 4);
                float2 ka = __half22float2(*(const __half2*)&kr.x);
                float2 kb = __half22float2(*(const __half2*)&kr.y);
                k4[j] = make_float4(ka.x, ka.y, kb.x, kb.y);
                float2 va = __half22float2(*(const __half2*)&vr.x);
                float2 vb = __half22float2(*(const __half2*)&vr.y);
                v4[j] = make_float4(va.x, va.y, vb.x, vb.y);
            }
            #pragma unroll
            for (int j = 0; j < 4; ++j) {
                float qk = q4.x * k4[j].x + q4.y * k4[j].y + q4.z * k4[j].z + q4.w * k4[j].w;
                ea0[j] = cosf(fmaf(relj[j], tww, tbb));
                u0[j] = ea0[j] * p00 + ea1[j] * p01 + ea2[j] * p02 + (h0lane ? qk : 0.f);
                u1[j] = ea0[j] * p10 + ea1[j] * p11 + ea2[j] * p12 + (h0lane ? 0.f : qk);
            }
            #pragma unroll
            for (int o = 16; o; o >>= 1) {
                #pragma unroll
                for (int j = 0; j < 4; ++j) {
                    u0[j] += __shfl_xor_sync(0xffffffffu, u0[j], o);
                    u1[j] += __shfl_xor_sync(0xffffffffu, u1[j], o);
                }
            }
            #pragma unroll
            for (int j = 0; j < 4; ++j) {
                if (j < nb) {
                    float e0 = __expf(u0[j] * 0.125f);
                    float e1 = __expf(u1[j] * 0.125f);
                    den0 += e0; den1 += e1;
                    float eh = h0lane ? e0 : e1;
                    aco.x = fmaf(v4[j].x, eh, aco.x);
                    aco.y = fmaf(v4[j].y, eh, aco.y);
                    aco.z = fmaf(v4[j].z, eh, aco.z);
                    aco.w = fmaf(v4[j].w, eh, aco.w);
                    as0.x = fmaf(ea0[j], e0, as0.x);  as0.y = fmaf(ea0[j], e1, as0.y);
                    as1.x = fmaf(ea1[j], e0, as1.x);  as1.y = fmaf(ea1[j], e1, as1.y);
                    as2.x = fmaf(ea2[j], e0, as2.x);  as2.y = fmaf(ea2[j], e1, as2.y);
                }
            }
        }

        float i0 = 1.0f / (den0 + 1e-16f);
        float i1 = 1.0f / (den1 + 1e-16f);

        // stage normalized s into per-warp smem: sS[d*2 + h]
        sS[lane * 2 + 0]        = as0.x * i0;  sS[lane * 2 + 1]        = as0.y * i1;
        sS[(lane + 32) * 2 + 0] = as1.x * i0;  sS[(lane + 32) * 2 + 1] = as1.y * i1;
        sS[(lane + 64) * 2 + 0] = as2.x * i0;  sS[(lane + 64) * 2 + 1] = as2.y * i1;
        __syncwarp();

        // matvec: r[c] = sum_d s[d][h(c)] * We[d][c], cols c = lane*4..lane*4+3
        unsigned long long a01 = 0ULL, a23 = 0ULL;
        const float4* w4 = (const float4*)sWe + lane;
        #pragma unroll 8
        for (int d = 0; d < 96; ++d) {
            float sv = sS[d * 2 + hsel];
            float4 w = w4[d * 32];
            unsigned long long svp = pk2(sv, sv);
            a01 = ffma2(pk2(w.x, w.y), svp, a01);
            a23 = ffma2(pk2(w.z, w.w), svp, a23);
        }
        __syncwarp();
        float2 r01 = upk2(a01), r23 = upk2(a23);

        float ih = h0lane ? i0 : i1;
        float4* op = (float4*)(out + (size_t)n * 128 + lane * 4);
        float4 o4 = __ldcs(op);
        o4.x += aco.x * ih + r01.x;
        o4.y += aco.y * ih + r01.y;
        o4.z += aco.z * ih + r23.x;
        o4.w += aco.w * ih + r23.y;
        __stcs(op, o4);
    }
}

// ------------------------- launch -------------------------
extern "C" void kernel_launch(void* const* d_in, const int* in_sizes, int n_in,
                              void* d_out, int out_size) {
    const float* x   = (const float*)d_in[0];
    const float* lu  = (const float*)d_in[1];
    const float* tv  = (const float*)d_in[2];
    const float* msg = (const float*)d_in[3];
    const int*   ei  = (const int*)d_in[4];
    const float* tw  = (const float*)d_in[5];
    const float* tb  = (const float*)d_in[6];
    const float* Wq  = (const float*)d_in[7];
    const float* bq  = (const float*)d_in[8];
    const float* Wk  = (const float*)d_in[9];
    const float* bk  = (const float*)d_in[10];
    const float* Wv  = (const float*)d_in[11];
    const float* bv  = (const float*)d_in[12];
    const float* We  = (const float*)d_in[13];
    const float* Ws  = (const float*)d_in[14];
    const float* bs  = (const float*)d_in[15];
    float* out = (float*)d_out;

    static cudaStream_t s2 = nullptr;
    static cudaEvent_t evFork = nullptr, evJoin = nullptr;
    if (!s2) {
        cudaFuncSetAttribute(k_gemm_mma, cudaFuncAttributeMaxDynamicSharedMemorySize, SM_TOT);
        cudaFuncSetAttribute(k_edge, cudaFuncAttributeMaxDynamicSharedMemorySize, SM_EDGE);
        cudaStreamCreateWithFlags(&s2, cudaStreamNonBlocking);
        cudaEventCreateWithFlags(&evFork, cudaEventDisableTiming);
        cudaEventCreateWithFlags(&evJoin, cudaEventDisableTiming);
    }

    const int nblk = (NN + 255) / 256;  // 391

    // Fork s2 off the main stream.
    cudaEventRecord(evFork, 0);
    cudaStreamWaitEvent(s2, evFork, 0);

    // Submission order chosen so index 3 = k_gemm_mma (ncu -s5 profiles idx 3).
    k_prep<<<128, 256>>>(Wq, bq, Wk, bk, Wv, bv, We, Ws, bs);         // idx 0 (main)
    k_init<<<nblk, 256, 0, s2>>>();                                   // idx 1 (s2)
    k_hist<<<(EE + 255) / 256, 256, 0, s2>>>(ei);                     // idx 2 (s2)
    k_gemm_mma<<<(NN + A_ROWS - 1) / A_ROWS, 256, SM_TOT>>>(x, out);  // idx 3 (main)
    k_scan_a<<<nblk, 256, 0, s2>>>();                                 // idx 4
    k_scan_b<<<1, 512, 0, s2>>>(nblk);                                // idx 5
    k_scan_c<<<nblk, 256, 0, s2>>>();                                 // idx 6
    k_permute<<<(EE + 255) / 256, 256, 0, s2>>>(ei, lu, tv);          // idx 7
    k_pmsg<<<(EE + 7) / 8, 256, 0, s2>>>(msg);                        // idx 8
    cudaEventRecord(evJoin, s2);

    // Join, then fused edge pass (attn + skip + s@We epilogue).
    cudaStreamWaitEvent(0, evJoin, 0);
    k_edge<<<EDGE_CTAS, 256, SM_EDGE>>>(tw, tb, We, out);             // idx 9
}

// round 12
// speedup vs baseline: 1.2018x; 1.2018x over previous
#include <cuda_runtime.h>
#include <cuda_fp16.h>
#include <math_constants.h>
#include <cstdint>

// Problem constants (fixed shapes)
#define NN 100000
#define EE 800000
#define WC 768   // fused weight cols: [q 128][k 128][v 128][skip 128][p0 96][p1 96][pad 64]

// ------------------------- device scratch -------------------------
__device__ __half g_dst[(size_t)NN * 320];           // per-node dst data: q[128], p[192] fp16
__device__ __half g_src[(size_t)NN * 256];           // per-node src data: k[128], v[128] fp16
__device__ __half g_whT[WC * 128];                   // W^T (fp16), [col][k]
__device__ float g_bias[WC];
// sort scratch (SoA sorted edge data)
__device__ int g_cnt[NN];
__device__ int g_off[NN + 1];
__device__ int g_cursor[NN];
__device__ int g_esrc[EE];
__device__ int g_eidx[EE];
__device__ float g_erel[EE];
__device__ int g_bsum[512];

// ------------------------- generic helpers -------------------------
__device__ __forceinline__ unsigned long long pk2(float lo, float hi) {
    unsigned long long r;
    asm("mov.b64 %0, {%1,%2};" : "=l"(r) : "f"(lo), "f"(hi));
    return r;
}
__device__ __forceinline__ float2 upk2(unsigned long long v) {
    float2 r;
    asm("mov.b64 {%0,%1}, %2;" : "=f"(r.x), "=f"(r.y) : "l"(v));
    return r;
}
__device__ __forceinline__ unsigned long long ffma2(unsigned long long a, unsigned long long b,
                                                    unsigned long long c) {
    unsigned long long d;
    asm("fma.rn.f32x2 %0, %1, %2, %3;" : "=l"(d) : "l"(a), "l"(b), "l"(c));
    return d;
}
__device__ __forceinline__ uint32_t smem_u32(const void* p) {
    uint32_t a;
    asm("{ .reg .u64 t; cvta.to.shared.u64 t, %1; cvt.u32.u64 %0, t; }" : "=r"(a) : "l"(p));
    return a;
}
__device__ __forceinline__ void ldsm4(uint32_t* r, uint32_t addr) {
    asm volatile("ldmatrix.sync.aligned.m8n8.x4.shared.b16 {%0,%1,%2,%3}, [%4];"
                 : "=r"(r[0]), "=r"(r[1]), "=r"(r[2]), "=r"(r[3]) : "r"(addr));
}
__device__ __forceinline__ void mma16816(float* c, const uint32_t* a, uint32_t b0, uint32_t b1) {
    asm volatile(
        "mma.sync.aligned.m16n8k16.row.col.f32.f16.f16.f32 "
        "{%0,%1,%2,%3}, {%4,%5,%6,%7}, {%8,%9}, {%0,%1,%2,%3};"
        : "+f"(c[0]), "+f"(c[1]), "+f"(c[2]), "+f"(c[3])
        : "r"(a[0]), "r"(a[1]), "r"(a[2]), "r"(a[3]), "r"(b0), "r"(b1));
}
__device__ __forceinline__ void cp16(uint32_t saddr, const void* g) {
    asm volatile("cp.async.cg.shared.global [%0], [%1], 16;" :: "r"(saddr), "l"(g));
}
#define CP_COMMIT() asm volatile("cp.async.commit_group;" ::: "memory")
#define CP_WAIT1()  asm volatile("cp.async.wait_group 1;" ::: "memory")
#define CP_WAIT0()  asm volatile("cp.async.wait_group 0;" ::: "memory")

// ------------------------- kernel: init sort scratch -------------------------
__global__ void k_init() {
    int i = blockIdx.x * blockDim.x + threadIdx.x;
    if (i < NN) {
        g_cnt[i] = 0;
        g_cursor[i] = 0;
    }
}

// ------------------------- kernel: fused weights (transposed, fp16) ----------
__global__ void k_prep(const float* __restrict__ Wq, const float* __restrict__ bq,
                       const float* __restrict__ Wk, const float* __restrict__ bk,
                       const float* __restrict__ Wv, const float* __restrict__ bv,
                       const float* __restrict__ We,
                       const float* __restrict__ Ws, const float* __restrict__ bs) {
    int i = blockIdx.x;  // 0..127 (input dim k)
    for (int c = threadIdx.x; c < WC; c += blockDim.x) {
        float w = 0.0f, b = 0.0f;
        if (c < 128)      { w = Wq[i * 128 + c];         b = bq[c]; }
        else if (c < 256) { w = Wk[i * 128 + (c - 128)]; b = bk[c - 128]; }
        else if (c < 384) { w = Wv[i * 128 + (c - 256)]; b = bv[c - 256]; }
        else if (c < 512) { w = Ws[i * 128 + (c - 384)]; b = bs[c - 384]; }
        else if (c < 704) {
            int hd = c - 512;
            int h = hd / 96, d = hd % 96;
            float acc = 0.0f, accb = 0.0f;
            #pragma unroll 8
            for (int cc = 0; cc < 64; ++cc) {
                float we = We[d * 128 + h * 64 + cc];
                acc = fmaf(Wq[i * 128 + h * 64 + cc], we, acc);
                accb = fmaf(bq[h * 64 + cc], we, accb);
            }
            w = acc; b = accb;
        }
        g_whT[c * 128 + i] = __float2half_rn(w);
        if (i == 0) g_bias[c] = b;
    }
}

// ------------------------- kernel: HMMA node GEMM (fp16 single-term) ---------
#define A_ROWS 64
#define A_STRIDE 136
#define B_STRIDE 72
#define SZ_A (A_ROWS * A_STRIDE * 2)      // 17408 (single fp16 A)
#define SZ_B (128 * B_STRIDE * 2)         // 18432 per buffer
#define SM_A    0
#define SM_B    (SZ_A)                    // 2 buffers
#define SM_BIAS (SZ_A + 2 * SZ_B)         // 54272
#define SM_TOT  (SM_BIAS + WC * 4)        // 57344

__device__ __forceinline__ void load_B_async(uint32_t sb, int s, int tid) {
    const int chunk = s >> 1, kh = s & 1;
    const uint32_t bbase = SM_B + (uint32_t)(s & 1) * SZ_B;
    for (int i = tid; i < 128 * 8; i += 256) {
        int c = i >> 3, seg = i & 7;
        size_t gsrc = (size_t)(chunk * 128 + c) * 128 + kh * 64 + seg * 8;
        uint32_t doff = (uint32_t)(c * (B_STRIDE * 2) + seg * 16);
        cp16(sb + bbase + doff, g_whT + gsrc);
    }
}

__global__ void __launch_bounds__(256, 3) k_gemm_mma(const float* __restrict__ x,
                                                     float* __restrict__ out) {
    extern __shared__ char smem[];
    const uint32_t sb = smem_u32(smem);
    const int tid = threadIdx.x, wid = tid >> 5, lane = tid & 31;
    const int row0 = blockIdx.x * A_ROWS;

    load_B_async(sb, 0, tid);
    CP_COMMIT();

    float* sbias = (float*)(smem + SM_BIAS);
    for (int i = tid; i < WC; i += 256) sbias[i] = g_bias[i];

    // load A tile [64x128] as single fp16
    for (int i = tid; i < A_ROWS * 32; i += 256) {
        int r = i >> 5, k4 = (i & 31) << 2;
        int row = row0 + r;
        float4 v = (row < NN) ? __ldcs((const float4*)(x + (size_t)row * 128 + k4))
                              : make_float4(0.f, 0.f, 0.f, 0.f);
        __half2 h01 = __floats2half2_rn(v.x, v.y);
        __half2 h23 = __floats2half2_rn(v.z, v.w);
        uint32_t off = (uint32_t)(r * (A_STRIDE * 2) + k4 * 2);
        *(uint2*)(smem + SM_A + off) = make_uint2(*(uint32_t*)&h01, *(uint32_t*)&h23);
    }

    const int wm = wid & 1, wn = wid >> 1;       // warp grid 2 x 4
    const int rw = wm * 32, cw = wn * 32;        // warp tile 32 x 32
    const uint32_t a_off = (uint32_t)((rw + (lane & 15)) * (A_STRIDE * 2) + (lane >> 4) * 16);
    const uint32_t b_off = (uint32_t)((cw + (lane & 15)) * (B_STRIDE * 2) + (lane >> 4) * 16);
    const int trow = lane >> 2;
    const int tcol = (lane & 3) * 2;

    float acc[2][4][4];

    for (int s = 0; s < 12; ++s) {
        const int chunk = s >> 1, kh = s & 1;
        if (kh == 0) {
            #pragma unroll
            for (int i = 0; i < 2; ++i)
                #pragma unroll
                for (int j = 0; j < 4; ++j)
                    #pragma unroll
                    for (int q = 0; q < 4; ++q) acc[i][j][q] = 0.0f;
        }
        if (s + 1 < 12) {
            load_B_async(sb, s + 1, tid);
            CP_COMMIT();
            CP_WAIT1();
        } else {
            CP_WAIT0();
        }
        __syncthreads();

        const uint32_t sA = sb + SM_A + kh * 128;
        const uint32_t sBh = sb + SM_B + (uint32_t)(s & 1) * SZ_B;
        #pragma unroll
        for (int ks = 0; ks < 4; ++ks) {
            uint32_t a[2][4], bh[2][4];
            #pragma unroll
            for (int i = 0; i < 2; ++i)
                ldsm4(a[i], sA + a_off + i * (16 * A_STRIDE * 2) + ks * 32);
            #pragma unroll
            for (int j16 = 0; j16 < 2; ++j16)
                ldsm4(bh[j16], sBh + b_off + j16 * (16 * B_STRIDE * 2) + ks * 32);
            #pragma unroll
            for (int i = 0; i < 2; ++i) {
                mma16816(acc[i][0], a[i], bh[0][0], bh[0][2]);
                mma16816(acc[i][1], a[i], bh[0][1], bh[0][3]);
                mma16816(acc[i][2], a[i], bh[1][0], bh[1][2]);
                mma16816(acc[i][3], a[i], bh[1][1], bh[1][3]);
            }
        }
        __syncthreads();

        if (kh == 1) {
            if (chunk == 3) {
                // skip -> out (fp32)
                #pragma unroll
                for (int i = 0; i < 2; ++i) {
                    int r = row0 + rw + i * 16 + trow;
                    #pragma unroll
                    for (int j = 0; j < 4; ++j) {
                        int G = 384 + cw + j * 8 + tcol;
                        float b0 = sbias[G], b1 = sbias[G + 1];
                        if (r < NN) {
                            float2 v = make_float2(acc[i][j][0] + b0, acc[i][j][1] + b1);
                            __stcs((float2*)(out + (size_t)r * 128 + (G - 384)), v);
                        }
                        if (r + 8 < NN) {
                            float2 v = make_float2(acc[i][j][2] + b0, acc[i][j][3] + b1);
                            __stcs((float2*)(out + (size_t)(r + 8) * 128 + (G - 384)), v);
                        }
                    }
                }
            } else {
                // q/p -> g_dst fp16, k/v -> g_src fp16
                __half* bp; int stride, sub;
                bool is_kv = (chunk == 1 || chunk == 2);
                if (chunk == 0)      { bp = g_dst; stride = 320; sub = 0;   }
                else if (is_kv)      { bp = g_src; stride = 256; sub = 128; }
                else                 { bp = g_dst; stride = 320; sub = 384; }
                #pragma unroll
                for (int i = 0; i < 2; ++i) {
                    int r = row0 + rw + i * 16 + trow;
                    #pragma unroll
                    for (int j = 0; j < 4; ++j) {
                        int G = chunk * 128 + cw + j * 8 + tcol;
                        if (G >= 704) continue;
                        float b0 = sbias[G], b1 = sbias[G + 1];
                        if (r < NN) {
                            __half2 hv = __floats2half2_rn(acc[i][j][0] + b0,
                                                           acc[i][j][1] + b1);
                            *(__half2*)(bp + (size_t)r * stride + (G - sub)) = hv;
                        }
                        if (r + 8 < NN) {
                            __half2 hv = __floats2half2_rn(acc[i][j][2] + b0,
                                                           acc[i][j][3] + b1);
                            *(__half2*)(bp + (size_t)(r + 8) * stride + (G - sub)) = hv;
                        }
                    }
                }
            }
        }
    }
}

// ------------------------- sort: histogram, scan, permute -------------------------
__global__ void k_hist(const int* __restrict__ ei) {
    int i = blockIdx.x * blockDim.x + threadIdx.x;
    if (i < EE) atomicAdd(&g_cnt[__ldcs(ei + EE + i)], 1);
}

__global__ void k_scan_a() {
    __shared__ int sm[256];
    int t = threadIdx.x;
    int gid = blockIdx.x * 256 + t;
    int val = (gid < NN) ? g_cnt[gid] : 0;
    sm[t] = val;
    __syncthreads();
    #pragma unroll
    for (int o = 1; o < 256; o <<= 1) {
        int add = (t >= o) ? sm[t - o] : 0;
        __syncthreads();
        sm[t] += add;
        __syncthreads();
    }
    if (gid < NN) g_off[gid] = sm[t] - val;
    if (t == 255) g_bsum[blockIdx.x] = sm[255];
}

__global__ void k_scan_b(int nblk) {
    __shared__ int sm[512];
    int t = threadIdx.x;
    int val = (t < nblk) ? g_bsum[t] : 0;
    sm[t] = val;
    __syncthreads();
    #pragma unroll
    for (int o = 1; o < 512; o <<= 1) {
        int add = (t >= o) ? sm[t - o] : 0;
        __syncthreads();
        sm[t] += add;
        __syncthreads();
    }
    if (t < nblk) g_bsum[t] = sm[t] - val;
}

__global__ void k_scan_c() {
    int gid = blockIdx.x * 256 + threadIdx.x;
    if (gid < NN) g_off[gid] += g_bsum[blockIdx.x];
    if (gid == 0) g_off[NN] = EE;
}

__global__ void k_permute(const int* __restrict__ ei, const float* __restrict__ lu,
                          const float* __restrict__ tv) {
    int i = blockIdx.x * blockDim.x + threadIdx.x;
    if (i >= EE) return;
    int d = __ldcs(ei + EE + i);
    int s = __ldcs(ei + i);
    int pos = g_off[d] + atomicAdd(&g_cursor[d], 1);
    g_esrc[pos] = s;
    g_eidx[pos] = i;
    g_erel[pos] = lu[s] - __ldcs(tv + i);
}

// ------------------------- kernel: fused edge pass + s@We epilogue -------------
// Persistent: 1480 CTAs, warp-per-node strided loop. We staged in smem per CTA.
#define EDGE_CTAS 1480
#define EDGE_WARPS (EDGE_CTAS * 8)
#define SM_EDGE ((96 * 128 + 8 * 192) * 4)   // We fp32 + per-warp s: 55296 B

__global__ void __launch_bounds__(256) k_edge(const float* __restrict__ msg,
                                              const float* __restrict__ time_w,
                                              const float* __restrict__ time_b,
                                              const float* __restrict__ We,
                                              float* __restrict__ out) {
    extern __shared__ float sme[];
    float* sWe = sme;                     // [96][128]
    const int tid = threadIdx.x, wid = tid >> 5, lane = tid & 31;

    for (int i = tid; i < 96 * 128 / 4; i += 256)
        ((float4*)sWe)[i] = ((const float4*)We)[i];
    __syncthreads();

    float* sS = sme + 96 * 128 + wid * 192;   // per-warp s[d][h]
    const float tww = time_w[lane], tbb = time_b[lane];
    const bool h0lane = (lane < 16);
    const int hsel = h0lane ? 0 : 1;

    for (int n = blockIdx.x * 8 + wid; n < NN; n += EDGE_WARPS) {
        const int off0 = g_off[n];
        const int deg = g_off[n + 1] - off0;
        if (deg == 0) continue;   // out already holds skip

        const __half* dp = g_dst + (size_t)n * 320;
        int2 qr = __ldcs((const int2*)(dp + lane * 4));
        float2 qa = __half22float2(*(const __half2*)&qr.x);
        float2 qb = __half22float2(*(const __half2*)&qr.y);
        const float4 q4 = make_float4(qa.x, qa.y, qb.x, qb.y);
        short ps0 = __ldcs((const short*)(dp + 128 + lane));
        short ps1 = __ldcs((const short*)(dp + 160 + lane));
        short ps2 = __ldcs((const short*)(dp + 192 + lane));
        short ps3 = __ldcs((const short*)(dp + 224 + lane));
        short ps4 = __ldcs((const short*)(dp + 256 + lane));
        short ps5 = __ldcs((const short*)(dp + 288 + lane));
        const float p00 = __half2float(*(__half*)&ps0), p01 = __half2float(*(__half*)&ps1);
        const float p02 = __half2float(*(__half*)&ps2), p10 = __half2float(*(__half*)&ps3);
        const float p11 = __half2float(*(__half*)&ps4), p12 = __half2float(*(__half*)&ps5);

        float den0 = 0.f, den1 = 0.f;
        float4 aco = make_float4(0.f, 0.f, 0.f, 0.f);
        float2 as0 = make_float2(0.f, 0.f), as1 = as0, as2 = as0;

        for (int eb = 0; eb < deg; eb += 4) {
            const int nb = deg - eb;
            int srcj[4], idxj[4];
            float relj[4], ea0[4], ea1[4], ea2[4], u0[4], u1[4];
            float4 k4[4], v4[4];
            #pragma unroll
            for (int j = 0; j < 4; ++j) {
                int pos = off0 + eb + ((j < nb) ? j : 0);
                srcj[j] = __ldcs(g_esrc + pos);
                idxj[j] = __ldcs(g_eidx + pos);
                relj[j] = __ldcs(g_erel + pos);
            }
            #pragma unroll
            for (int j = 0; j < 4; ++j) {
                const __half* sp = g_src + (size_t)srcj[j] * 256;
                uint2 kr = *(const uint2*)(sp + lane * 4);     // cached: reused ~8x
                uint2 vr = *(const uint2*)(sp + 128 + lane * 4);
                float2 ka = __half22float2(*(const __half2*)&kr.x);
                float2 kb = __half22float2(*(const __half2*)&kr.y);
                k4[j] = make_float4(ka.x, ka.y, kb.x, kb.y);
                float2 va = __half22float2(*(const __half2*)&vr.x);
                float2 vb = __half22float2(*(const __half2*)&vr.y);
                v4[j] = make_float4(va.x, va.y, vb.x, vb.y);
                ea1[j] = __ldcs(msg + (size_t)idxj[j] * 64 + lane);
                ea2[j] = __ldcs(msg + (size_t)idxj[j] * 64 + 32 + lane);
            }
            #pragma unroll
            for (int j = 0; j < 4; ++j) {
                float qk = q4.x * k4[j].x + q4.y * k4[j].y + q4.z * k4[j].z + q4.w * k4[j].w;
                ea0[j] = cosf(fmaf(relj[j], tww, tbb));
                u0[j] = ea0[j] * p00 + ea1[j] * p01 + ea2[j] * p02 + (h0lane ? qk : 0.f);
                u1[j] = ea0[j] * p10 + ea1[j] * p11 + ea2[j] * p12 + (h0lane ? 0.f : qk);
            }
            #pragma unroll
            for (int o = 16; o; o >>= 1) {
                #pragma unroll
                for (int j = 0; j < 4; ++j) {
                    u0[j] += __shfl_xor_sync(0xffffffffu, u0[j], o);
                    u1[j] += __shfl_xor_sync(0xffffffffu, u1[j], o);
                }
            }
            #pragma unroll
            for (int j = 0; j < 4; ++j) {
                if (j < nb) {
                    float e0 = __expf(u0[j] * 0.125f);
                    float e1 = __expf(u1[j] * 0.125f);
                    den0 += e0; den1 += e1;
                    float eh = h0lane ? e0 : e1;
                    aco.x = fmaf(v4[j].x, eh, aco.x);
                    aco.y = fmaf(v4[j].y, eh, aco.y);
                    aco.z = fmaf(v4[j].z, eh, aco.z);
                    aco.w = fmaf(v4[j].w, eh, aco.w);
                    as0.x = fmaf(ea0[j], e0, as0.x);  as0.y = fmaf(ea0[j], e1, as0.y);
                    as1.x = fmaf(ea1[j], e0, as1.x);  as1.y = fmaf(ea1[j], e1, as1.y);
                    as2.x = fmaf(ea2[j], e0, as2.x);  as2.y = fmaf(ea2[j], e1, as2.y);
                }
            }
        }

        float i0 = 1.0f / (den0 + 1e-16f);
        float i1 = 1.0f / (den1 + 1e-16f);

        // stage normalized s into per-warp smem: sS[d*2 + h]
        sS[lane * 2 + 0]        = as0.x * i0;  sS[lane * 2 + 1]        = as0.y * i1;
        sS[(lane + 32) * 2 + 0] = as1.x * i0;  sS[(lane + 32) * 2 + 1] = as1.y * i1;
        sS[(lane + 64) * 2 + 0] = as2.x * i0;  sS[(lane + 64) * 2 + 1] = as2.y * i1;
        __syncwarp();

        // matvec: r[c] = sum_d s[d][h(c)] * We[d][c], cols c = lane*4..lane*4+3
        unsigned long long a01 = 0ULL, a23 = 0ULL;
        const float4* w4 = (const float4*)sWe + lane;
        #pragma unroll 8
        for (int d = 0; d < 96; ++d) {
            float sv = sS[d * 2 + hsel];
            float4 w = w4[d * 32];
            unsigned long long svp = pk2(sv, sv);
            a01 = ffma2(pk2(w.x, w.y), svp, a01);
            a23 = ffma2(pk2(w.z, w.w), svp, a23);
        }
        __syncwarp();
        float2 r01 = upk2(a01), r23 = upk2(a23);

        float ih = h0lane ? i0 : i1;
        float4* op = (float4*)(out + (size_t)n * 128 + lane * 4);
        float4 o4 = __ldcs(op);
        o4.x += aco.x * ih + r01.x;
        o4.y += aco.y * ih + r01.y;
        o4.z += aco.z * ih + r23.x;
        o4.w += aco.w * ih + r23.y;
        __stcs(op, o4);
    }
}

// ------------------------- launch -------------------------
extern "C" void kernel_launch(void* const* d_in, const int* in_sizes, int n_in,
                              void* d_out, int out_size) {
    const float* x   = (const float*)d_in[0];
    const float* lu  = (const float*)d_in[1];
    const float* tv  = (const float*)d_in[2];
    const float* msg = (const float*)d_in[3];
    const int*   ei  = (const int*)d_in[4];
    const float* tw  = (const float*)d_in[5];
    const float* tb  = (const float*)d_in[6];
    const float* Wq  = (const float*)d_in[7];
    const float* bq  = (const float*)d_in[8];
    const float* Wk  = (const float*)d_in[9];
    const float* bk  = (const float*)d_in[10];
    const float* Wv  = (const float*)d_in[11];
    const float* bv  = (const float*)d_in[12];
    const float* We  = (const float*)d_in[13];
    const float* Ws  = (const float*)d_in[14];
    const float* bs  = (const float*)d_in[15];
    float* out = (float*)d_out;

    static cudaStream_t s2 = nullptr;
    static cudaEvent_t evFork = nullptr, evJoin = nullptr;
    if (!s2) {
        cudaFuncSetAttribute(k_gemm_mma, cudaFuncAttributeMaxDynamicSharedMemorySize, SM_TOT);
        cudaFuncSetAttribute(k_edge, cudaFuncAttributeMaxDynamicSharedMemorySize, SM_EDGE);
        cudaStreamCreateWithFlags(&s2, cudaStreamNonBlocking);
        cudaEventCreateWithFlags(&evFork, cudaEventDisableTiming);
        cudaEventCreateWithFlags(&evJoin, cudaEventDisableTiming);
    }

    const int nblk = (NN + 255) / 256;  // 391

    // Fork s2 off the main stream.
    cudaEventRecord(evFork, 0);
    cudaStreamWaitEvent(s2, evFork, 0);

    // Submission order chosen so index 3 = k_gemm_mma (ncu -s5 profiles idx 3).
    k_prep<<<128, 256>>>(Wq, bq, Wk, bk, Wv, bv, We, Ws, bs);         // idx 0 (main)
    k_init<<<nblk, 256, 0, s2>>>();                                   // idx 1 (s2)
    k_hist<<<(EE + 255) / 256, 256, 0, s2>>>(ei);                     // idx 2 (s2)
    k_gemm_mma<<<(NN + A_ROWS - 1) / A_ROWS, 256, SM_TOT>>>(x, out);  // idx 3 (main)
    k_scan_a<<<nblk, 256, 0, s2>>>();                                 // idx 4
    k_scan_b<<<1, 512, 0, s2>>>(nblk);                                // idx 5
    k_scan_c<<<nblk, 256, 0, s2>>>();                                 // idx 6
    k_permute<<<(EE + 255) / 256, 256, 0, s2>>>(ei, lu, tv);          // idx 7
    cudaEventRecord(evJoin, s2);

    // Join, then fused edge pass (attn + skip + s@We epilogue).
    cudaStreamWaitEvent(0, evJoin, 0);
    k_edge<<<EDGE_CTAS, 256, SM_EDGE>>>(msg, tw, tb, We, out);        // idx 8
}

// round 13
// speedup vs baseline: 1.2637x; 1.0515x over previous
#include <cuda_runtime.h>
#include <cuda_fp16.h>
#include <math_constants.h>
#include <cstdint>

// Problem constants (fixed shapes)
#define NN 100000
#define EE 800000
#define WC 768   // fused weight cols: [q 128][k 128][v 128][skip 128][p0 96][p1 96][pad 64]

// ------------------------- device scratch -------------------------
__device__ __half g_dst[(size_t)NN * 320];           // per-node dst data: q[128], p[192] fp16
__device__ __half g_src[(size_t)NN * 256];           // per-node src data: k[128], v[128] fp16
__device__ __half g_whT[WC * 128];                   // W^T (fp16), [col][k]
__device__ float g_bias[WC];
// sort scratch (SoA sorted edge data)
__device__ int g_cnt[NN];
__device__ int g_off[NN + 1];
__device__ int g_cursor[NN];
__device__ int g_esrc[EE];
__device__ int g_eidx[EE];
__device__ float g_erel[EE];
__device__ int g_bsum[512];

// ------------------------- generic helpers -------------------------
__device__ __forceinline__ unsigned long long pk2(float lo, float hi) {
    unsigned long long r;
    asm("mov.b64 %0, {%1,%2};" : "=l"(r) : "f"(lo), "f"(hi));
    return r;
}
__device__ __forceinline__ float2 upk2(unsigned long long v) {
    float2 r;
    asm("mov.b64 {%0,%1}, %2;" : "=f"(r.x), "=f"(r.y) : "l"(v));
    return r;
}
__device__ __forceinline__ unsigned long long ffma2(unsigned long long a, unsigned long long b,
                                                    unsigned long long c) {
    unsigned long long d;
    asm("fma.rn.f32x2 %0, %1, %2, %3;" : "=l"(d) : "l"(a), "l"(b), "l"(c));
    return d;
}
__device__ __forceinline__ uint32_t smem_u32(const void* p) {
    uint32_t a;
    asm("{ .reg .u64 t; cvta.to.shared.u64 t, %1; cvt.u32.u64 %0, t; }" : "=r"(a) : "l"(p));
    return a;
}
__device__ __forceinline__ void ldsm4(uint32_t* r, uint32_t addr) {
    asm volatile("ldmatrix.sync.aligned.m8n8.x4.shared.b16 {%0,%1,%2,%3}, [%4];"
                 : "=r"(r[0]), "=r"(r[1]), "=r"(r[2]), "=r"(r[3]) : "r"(addr));
}
__device__ __forceinline__ void mma16816(float* c, const uint32_t* a, uint32_t b0, uint32_t b1) {
    asm volatile(
        "mma.sync.aligned.m16n8k16.row.col.f32.f16.f16.f32 "
        "{%0,%1,%2,%3}, {%4,%5,%6,%7}, {%8,%9}, {%0,%1,%2,%3};"
        : "+f"(c[0]), "+f"(c[1]), "+f"(c[2]), "+f"(c[3])
        : "r"(a[0]), "r"(a[1]), "r"(a[2]), "r"(a[3]), "r"(b0), "r"(b1));
}
__device__ __forceinline__ void cp16(uint32_t saddr, const void* g) {
    asm volatile("cp.async.cg.shared.global [%0], [%1], 16;" :: "r"(saddr), "l"(g));
}
#define CP_COMMIT() asm volatile("cp.async.commit_group;" ::: "memory")
#define CP_WAIT1()  asm volatile("cp.async.wait_group 1;" ::: "memory")
#define CP_WAIT0()  asm volatile("cp.async.wait_group 0;" ::: "memory")

// ------------------------- kernel: init sort scratch -------------------------
__global__ void k_init() {
    int i = blockIdx.x * blockDim.x + threadIdx.x;
    if (i < NN) {
        g_cnt[i] = 0;
        g_cursor[i] = 0;
    }
}

// ------------------------- kernel: fused weights (transposed, fp16) ----------
__global__ void k_prep(const float* __restrict__ Wq, const float* __restrict__ bq,
                       const float* __restrict__ Wk, const float* __restrict__ bk,
                       const float* __restrict__ Wv, const float* __restrict__ bv,
                       const float* __restrict__ We,
                       const float* __restrict__ Ws, const float* __restrict__ bs) {
    int i = blockIdx.x;  // 0..127 (input dim k)
    for (int c = threadIdx.x; c < WC; c += blockDim.x) {
        float w = 0.0f, b = 0.0f;
        if (c < 128)      { w = Wq[i * 128 + c];         b = bq[c]; }
        else if (c < 256) { w = Wk[i * 128 + (c - 128)]; b = bk[c - 128]; }
        else if (c < 384) { w = Wv[i * 128 + (c - 256)]; b = bv[c - 256]; }
        else if (c < 512) { w = Ws[i * 128 + (c - 384)]; b = bs[c - 384]; }
        else if (c < 704) {
            int hd = c - 512;
            int h = hd / 96, d = hd % 96;
            float acc = 0.0f, accb = 0.0f;
            #pragma unroll 8
            for (int cc = 0; cc < 64; ++cc) {
                float we = We[d * 128 + h * 64 + cc];
                acc = fmaf(Wq[i * 128 + h * 64 + cc], we, acc);
                accb = fmaf(bq[h * 64 + cc], we, accb);
            }
            w = acc; b = accb;
        }
        g_whT[c * 128 + i] = __float2half_rn(w);
        if (i == 0) g_bias[c] = b;
    }
}

// ------------------------- kernel: HMMA node GEMM (fp16 single-term) ---------
#define A_ROWS 64
#define A_STRIDE 136
#define B_STRIDE 72
#define SZ_A (A_ROWS * A_STRIDE * 2)      // 17408 (single fp16 A)
#define SZ_B (128 * B_STRIDE * 2)         // 18432 per buffer
#define SM_A    0
#define SM_B    (SZ_A)                    // 2 buffers
#define SM_BIAS (SZ_A + 2 * SZ_B)         // 54272
#define SM_TOT  (SM_BIAS + WC * 4)        // 57344

__device__ __forceinline__ void load_B_async(uint32_t sb, int s, int tid) {
    const int chunk = s >> 1, kh = s & 1;
    const uint32_t bbase = SM_B + (uint32_t)(s & 1) * SZ_B;
    for (int i = tid; i < 128 * 8; i += 256) {
        int c = i >> 3, seg = i & 7;
        size_t gsrc = (size_t)(chunk * 128 + c) * 128 + kh * 64 + seg * 8;
        uint32_t doff = (uint32_t)(c * (B_STRIDE * 2) + seg * 16);
        cp16(sb + bbase + doff, g_whT + gsrc);
    }
}

__global__ void __launch_bounds__(256, 3) k_gemm_mma(const float* __restrict__ x,
                                                     float* __restrict__ out) {
    extern __shared__ char smem[];
    const uint32_t sb = smem_u32(smem);
    const int tid = threadIdx.x, wid = tid >> 5, lane = tid & 31;
    const int row0 = blockIdx.x * A_ROWS;

    load_B_async(sb, 0, tid);
    CP_COMMIT();

    float* sbias = (float*)(smem + SM_BIAS);
    for (int i = tid; i < WC; i += 256) sbias[i] = g_bias[i];

    // load A tile [64x128] as single fp16
    for (int i = tid; i < A_ROWS * 32; i += 256) {
        int r = i >> 5, k4 = (i & 31) << 2;
        int row = row0 + r;
        float4 v = (row < NN) ? __ldcs((const float4*)(x + (size_t)row * 128 + k4))
                              : make_float4(0.f, 0.f, 0.f, 0.f);
        __half2 h01 = __floats2half2_rn(v.x, v.y);
        __half2 h23 = __floats2half2_rn(v.z, v.w);
        uint32_t off = (uint32_t)(r * (A_STRIDE * 2) + k4 * 2);
        *(uint2*)(smem + SM_A + off) = make_uint2(*(uint32_t*)&h01, *(uint32_t*)&h23);
    }

    const int wm = wid & 1, wn = wid >> 1;       // warp grid 2 x 4
    const int rw = wm * 32, cw = wn * 32;        // warp tile 32 x 32
    const uint32_t a_off = (uint32_t)((rw + (lane & 15)) * (A_STRIDE * 2) + (lane >> 4) * 16);
    const uint32_t b_off = (uint32_t)((cw + (lane & 15)) * (B_STRIDE * 2) + (lane >> 4) * 16);
    const int trow = lane >> 2;
    const int tcol = (lane & 3) * 2;

    float acc[2][4][4];

    for (int s = 0; s < 12; ++s) {
        const int chunk = s >> 1, kh = s & 1;
        if (kh == 0) {
            #pragma unroll
            for (int i = 0; i < 2; ++i)
                #pragma unroll
                for (int j = 0; j < 4; ++j)
                    #pragma unroll
                    for (int q = 0; q < 4; ++q) acc[i][j][q] = 0.0f;
        }
        if (s + 1 < 12) {
            load_B_async(sb, s + 1, tid);
            CP_COMMIT();
            CP_WAIT1();
        } else {
            CP_WAIT0();
        }
        __syncthreads();

        const uint32_t sA = sb + SM_A + kh * 128;
        const uint32_t sBh = sb + SM_B + (uint32_t)(s & 1) * SZ_B;
        #pragma unroll
        for (int ks = 0; ks < 4; ++ks) {
            uint32_t a[2][4], bh[2][4];
            #pragma unroll
            for (int i = 0; i < 2; ++i)
                ldsm4(a[i], sA + a_off + i * (16 * A_STRIDE * 2) + ks * 32);
            #pragma unroll
            for (int j16 = 0; j16 < 2; ++j16)
                ldsm4(bh[j16], sBh + b_off + j16 * (16 * B_STRIDE * 2) + ks * 32);
            #pragma unroll
            for (int i = 0; i < 2; ++i) {
                mma16816(acc[i][0], a[i], bh[0][0], bh[0][2]);
                mma16816(acc[i][1], a[i], bh[0][1], bh[0][3]);
                mma16816(acc[i][2], a[i], bh[1][0], bh[1][2]);
                mma16816(acc[i][3], a[i], bh[1][1], bh[1][3]);
            }
        }
        __syncthreads();

        if (kh == 1) {
            if (chunk == 3) {
                // skip -> out (fp32)
                #pragma unroll
                for (int i = 0; i < 2; ++i) {
                    int r = row0 + rw + i * 16 + trow;
                    #pragma unroll
                    for (int j = 0; j < 4; ++j) {
                        int G = 384 + cw + j * 8 + tcol;
                        float b0 = sbias[G], b1 = sbias[G + 1];
                        if (r < NN) {
                            float2 v = make_float2(acc[i][j][0] + b0, acc[i][j][1] + b1);
                            __stcs((float2*)(out + (size_t)r * 128 + (G - 384)), v);
                        }
                        if (r + 8 < NN) {
                            float2 v = make_float2(acc[i][j][2] + b0, acc[i][j][3] + b1);
                            __stcs((float2*)(out + (size_t)(r + 8) * 128 + (G - 384)), v);
                        }
                    }
                }
            } else {
                // q/p -> g_dst fp16, k/v -> g_src fp16
                __half* bp; int stride, sub;
                bool is_kv = (chunk == 1 || chunk == 2);
                if (chunk == 0)      { bp = g_dst; stride = 320; sub = 0;   }
                else if (is_kv)      { bp = g_src; stride = 256; sub = 128; }
                else                 { bp = g_dst; stride = 320; sub = 384; }
                #pragma unroll
                for (int i = 0; i < 2; ++i) {
                    int r = row0 + rw + i * 16 + trow;
                    #pragma unroll
                    for (int j = 0; j < 4; ++j) {
                        int G = chunk * 128 + cw + j * 8 + tcol;
                        if (G >= 704) continue;
                        float b0 = sbias[G], b1 = sbias[G + 1];
                        if (r < NN) {
                            __half2 hv = __floats2half2_rn(acc[i][j][0] + b0,
                                                           acc[i][j][1] + b1);
                            *(__half2*)(bp + (size_t)r * stride + (G - sub)) = hv;
                        }
                        if (r + 8 < NN) {
                            __half2 hv = __floats2half2_rn(acc[i][j][2] + b0,
                                                           acc[i][j][3] + b1);
                            *(__half2*)(bp + (size_t)(r + 8) * stride + (G - sub)) = hv;
                        }
                    }
                }
            }
        }
    }
}

// ------------------------- sort: histogram, scan, permute -------------------------
__global__ void k_hist(const int* __restrict__ ei) {
    int i = blockIdx.x * blockDim.x + threadIdx.x;
    if (i < EE) atomicAdd(&g_cnt[__ldcs(ei + EE + i)], 1);
}

__global__ void k_scan_a() {
    __shared__ int sm[256];
    int t = threadIdx.x;
    int gid = blockIdx.x * 256 + t;
    int val = (gid < NN) ? g_cnt[gid] : 0;
    sm[t] = val;
    __syncthreads();
    #pragma unroll
    for (int o = 1; o < 256; o <<= 1) {
        int add = (t >= o) ? sm[t - o] : 0;
        __syncthreads();
        sm[t] += add;
        __syncthreads();
    }
    if (gid < NN) g_off[gid] = sm[t] - val;
    if (t == 255) g_bsum[blockIdx.x] = sm[255];
}

__global__ void k_scan_b(int nblk) {
    __shared__ int sm[512];
    int t = threadIdx.x;
    int val = (t < nblk) ? g_bsum[t] : 0;
    sm[t] = val;
    __syncthreads();
    #pragma unroll
    for (int o = 1; o < 512; o <<= 1) {
        int add = (t >= o) ? sm[t - o] : 0;
        __syncthreads();
        sm[t] += add;
        __syncthreads();
    }
    if (t < nblk) g_bsum[t] = sm[t] - val;
}

__global__ void k_scan_c() {
    int gid = blockIdx.x * 256 + threadIdx.x;
    if (gid < NN) g_off[gid] += g_bsum[blockIdx.x];
    if (gid == 0) g_off[NN] = EE;
}

__global__ void k_permute(const int* __restrict__ ei, const float* __restrict__ lu,
                          const float* __restrict__ tv) {
    int i = blockIdx.x * blockDim.x + threadIdx.x;
    if (i >= EE) return;
    int d = __ldcs(ei + EE + i);
    int s = __ldcs(ei + i);
    int pos = g_off[d] + atomicAdd(&g_cursor[d], 1);
    g_esrc[pos] = s;
    g_eidx[pos] = i;
    g_erel[pos] = lu[s] - __ldcs(tv + i);
}

// ------------------------- kernel: fused edge pass + s@We epilogue -------------
// Persistent: 1480 CTAs, warp-per-node strided loop. We staged in smem per CTA.
// half2 qk dot; 28-shuffle joint reduction; min-blocks 3 for occupancy.
#define EDGE_CTAS 1480
#define EDGE_WARPS (EDGE_CTAS * 8)
#define SM_EDGE ((96 * 128 + 8 * 192) * 4)   // We fp32 + per-warp s: 55296 B

__global__ void __launch_bounds__(256, 3) k_edge(const float* __restrict__ msg,
                                                 const float* __restrict__ time_w,
                                                 const float* __restrict__ time_b,
                                                 const float* __restrict__ We,
                                                 float* __restrict__ out) {
    extern __shared__ float sme[];
    float* sWe = sme;                     // [96][128]
    const int tid = threadIdx.x, wid = tid >> 5, lane = tid & 31;

    for (int i = tid; i < 96 * 128 / 4; i += 256)
        ((float4*)sWe)[i] = ((const float4*)We)[i];
    __syncthreads();

    float* sS = sme + 96 * 128 + wid * 192;   // per-warp s[d][h]
    const float tww = time_w[lane], tbb = time_b[lane];
    const bool h0lane = (lane < 16);
    const int hsel = h0lane ? 0 : 1;

    for (int n = blockIdx.x * 8 + wid; n < NN; n += EDGE_WARPS) {
        const int off0 = g_off[n];
        const int deg = g_off[n + 1] - off0;
        if (deg == 0) continue;   // out already holds skip

        const __half* dp = g_dst + (size_t)n * 320;
        uint2 qr = __ldcs((const uint2*)(dp + lane * 4));
        const __half2 qh01 = *(const __half2*)&qr.x;
        const __half2 qh23 = *(const __half2*)&qr.y;
        short ps0 = __ldcs((const short*)(dp + 128 + lane));
        short ps1 = __ldcs((const short*)(dp + 160 + lane));
        short ps2 = __ldcs((const short*)(dp + 192 + lane));
        short ps3 = __ldcs((const short*)(dp + 224 + lane));
        short ps4 = __ldcs((const short*)(dp + 256 + lane));
        short ps5 = __ldcs((const short*)(dp + 288 + lane));
        const float p00 = __half2float(*(__half*)&ps0), p01 = __half2float(*(__half*)&ps1);
        const float p02 = __half2float(*(__half*)&ps2), p10 = __half2float(*(__half*)&ps3);
        const float p11 = __half2float(*(__half*)&ps4), p12 = __half2float(*(__half*)&ps5);

        float den0 = 0.f, den1 = 0.f;
        float4 aco = make_float4(0.f, 0.f, 0.f, 0.f);
        float2 as0 = make_float2(0.f, 0.f), as1 = as0, as2 = as0;

        for (int eb = 0; eb < deg; eb += 4) {
            const int nb = deg - eb;
            int idxj[4];
            float relj[4], ea0[4], ea1[4], ea2[4], u0[4], u1[4];
            uint2 kr[4], vr[4];
            #pragma unroll
            for (int j = 0; j < 4; ++j) {
                int pos = off0 + eb + ((j < nb) ? j : 0);
                int src = __ldcs(g_esrc + pos);
                idxj[j] = __ldcs(g_eidx + pos);
                relj[j] = __ldcs(g_erel + pos);
                const __half* sp = g_src + (size_t)src * 256;
                kr[j] = *(const uint2*)(sp + lane * 4);        // cached: reused ~8x
                vr[j] = *(const uint2*)(sp + 128 + lane * 4);
            }
            #pragma unroll
            for (int j = 0; j < 4; ++j) {
                ea1[j] = __ldcs(msg + (size_t)idxj[j] * 64 + lane);
                ea2[j] = __ldcs(msg + (size_t)idxj[j] * 64 + 32 + lane);
            }
            #pragma unroll
            for (int j = 0; j < 4; ++j) {
                // half2 dot: q . k over this lane's 4 channels
                __half2 t = __hmul2(qh01, *(const __half2*)&kr[j].x);
                t = __hfma2(qh23, *(const __half2*)&kr[j].y, t);
                float2 tf = __half22float2(t);
                float qk = tf.x + tf.y;
                ea0[j] = cosf(fmaf(relj[j], tww, tbb));
                u0[j] = ea0[j] * p00 + ea1[j] * p01 + ea2[j] * p02 + (h0lane ? qk : 0.f);
                u1[j] = ea0[j] * p10 + ea1[j] * p11 + ea2[j] * p12 + (h0lane ? 0.f : qk);
            }
            // joint reduction: one o=16 step on all 8, fold into w (own head per
            // half-warp), 4 steps within halves, final exchange for other head.
            float w[4], oth[4];
            #pragma unroll
            for (int j = 0; j < 4; ++j) {
                u0[j] += __shfl_xor_sync(0xffffffffu, u0[j], 16);
                u1[j] += __shfl_xor_sync(0xffffffffu, u1[j], 16);
                w[j] = h0lane ? u0[j] : u1[j];
            }
            #pragma unroll
            for (int o = 8; o; o >>= 1) {
                #pragma unroll
                for (int j = 0; j < 4; ++j)
                    w[j] += __shfl_xor_sync(0xffffffffu, w[j], o);
            }
            #pragma unroll
            for (int j = 0; j < 4; ++j)
                oth[j] = __shfl_xor_sync(0xffffffffu, w[j], 16);

            #pragma unroll
            for (int j = 0; j < 4; ++j) {
                if (j < nb) {
                    float eo = __expf(w[j] * 0.125f);     // own head's exp
                    float ex = __expf(oth[j] * 0.125f);   // other head's exp
                    float e0 = h0lane ? eo : ex;
                    float e1 = h0lane ? ex : eo;
                    den0 += e0; den1 += e1;
                    float2 va = __half22float2(*(const __half2*)&vr[j].x);
                    float2 vb = __half22float2(*(const __half2*)&vr[j].y);
                    aco.x = fmaf(va.x, eo, aco.x);
                    aco.y = fmaf(va.y, eo, aco.y);
                    aco.z = fmaf(vb.x, eo, aco.z);
                    aco.w = fmaf(vb.y, eo, aco.w);
                    as0.x = fmaf(ea0[j], e0, as0.x);  as0.y = fmaf(ea0[j], e1, as0.y);
                    as1.x = fmaf(ea1[j], e0, as1.x);  as1.y = fmaf(ea1[j], e1, as1.y);
                    as2.x = fmaf(ea2[j], e0, as2.x);  as2.y = fmaf(ea2[j], e1, as2.y);
                }
            }
        }

        float i0 = 1.0f / (den0 + 1e-16f);
        float i1 = 1.0f / (den1 + 1e-16f);

        // stage normalized s into per-warp smem: sS[d*2 + h]
        sS[lane * 2 + 0]        = as0.x * i0;  sS[lane * 2 + 1]        = as0.y * i1;
        sS[(lane + 32) * 2 + 0] = as1.x * i0;  sS[(lane + 32) * 2 + 1] = as1.y * i1;
        sS[(lane + 64) * 2 + 0] = as2.x * i0;  sS[(lane + 64) * 2 + 1] = as2.y * i1;
        __syncwarp();

        // matvec: r[c] = sum_d s[d][h(c)] * We[d][c], cols c = lane*4..lane*4+3
        unsigned long long a01 = 0ULL, a23 = 0ULL;
        const float4* w4 = (const float4*)sWe + lane;
        #pragma unroll 8
        for (int d = 0; d < 96; ++d) {
            float sv = sS[d * 2 + hsel];
            float4 w = w4[d * 32];
            unsigned long long svp = pk2(sv, sv);
            a01 = ffma2(pk2(w.x, w.y), svp, a01);
            a23 = ffma2(pk2(w.z, w.w), svp, a23);
        }
        __syncwarp();
        float2 r01 = upk2(a01), r23 = upk2(a23);

        float ih = h0lane ? i0 : i1;
        float4* op = (float4*)(out + (size_t)n * 128 + lane * 4);
        float4 o4 = __ldcs(op);
        o4.x += aco.x * ih + r01.x;
        o4.y += aco.y * ih + r01.y;
        o4.z += aco.z * ih + r23.x;
        o4.w += aco.w * ih + r23.y;
        __stcs(op, o4);
    }
}

// ------------------------- launch -------------------------
extern "C" void kernel_launch(void* const* d_in, const int* in_sizes, int n_in,
                              void* d_out, int out_size) {
    const float* x   = (const float*)d_in[0];
    const float* lu  = (const float*)d_in[1];
    const float* tv  = (const float*)d_in[2];
    const float* msg = (const float*)d_in[3];
    const int*   ei  = (const int*)d_in[4];
    const float* tw  = (const float*)d_in[5];
    const float* tb  = (const float*)d_in[6];
    const float* Wq  = (const float*)d_in[7];
    const float* bq  = (const float*)d_in[8];
    const float* Wk  = (const float*)d_in[9];
    const float* bk  = (const float*)d_in[10];
    const float* Wv  = (const float*)d_in[11];
    const float* bv  = (const float*)d_in[12];
    const float* We  = (const float*)d_in[13];
    const float* Ws  = (const float*)d_in[14];
    const float* bs  = (const float*)d_in[15];
    float* out = (float*)d_out;

    static cudaStream_t s2 = nullptr;
    static cudaEvent_t evFork = nullptr, evJoin = nullptr;
    if (!s2) {
        cudaFuncSetAttribute(k_gemm_mma, cudaFuncAttributeMaxDynamicSharedMemorySize, SM_TOT);
        cudaFuncSetAttribute(k_edge, cudaFuncAttributeMaxDynamicSharedMemorySize, SM_EDGE);
        cudaStreamCreateWithFlags(&s2, cudaStreamNonBlocking);
        cudaEventCreateWithFlags(&evFork, cudaEventDisableTiming);
        cudaEventCreateWithFlags(&evJoin, cudaEventDisableTiming);
    }

    const int nblk = (NN + 255) / 256;  // 391

    // Fork s2 off the main stream.
    cudaEventRecord(evFork, 0);
    cudaStreamWaitEvent(s2, evFork, 0);

    // Submission order chosen so index 3 = k_gemm_mma (ncu -s5 profiles idx 3).
    k_prep<<<128, 256>>>(Wq, bq, Wk, bk, Wv, bv, We, Ws, bs);         // idx 0 (main)
    k_init<<<nblk, 256, 0, s2>>>();                                   // idx 1 (s2)
    k_hist<<<(EE + 255) / 256, 256, 0, s2>>>(ei);                     // idx 2 (s2)
    k_gemm_mma<<<(NN + A_ROWS - 1) / A_ROWS, 256, SM_TOT>>>(x, out);  // idx 3 (main)
    k_scan_a<<<nblk, 256, 0, s2>>>();                                 // idx 4
    k_scan_b<<<1, 512, 0, s2>>>(nblk);                                // idx 5
    k_scan_c<<<nblk, 256, 0, s2>>>();                                 // idx 6
    k_permute<<<(EE + 255) / 256, 256, 0, s2>>>(ei, lu, tv);          // idx 7
    cudaEventRecord(evJoin, s2);

    // Join, then fused edge pass (attn + skip + s@We epilogue).
    cudaStreamWaitEvent(0, evJoin, 0);
    k_edge<<<EDGE_CTAS, 256, SM_EDGE>>>(msg, tw, tb, We, out);        // idx 8
}

// round 14
// speedup vs baseline: 1.2683x; 1.0037x over previous
#include <cuda_runtime.h>
#include <cuda_fp16.h>
#include <math_constants.h>
#include <cstdint>

// Problem constants (fixed shapes)
#define NN 100000
#define EE 800000
#define WC 768   // fused weight cols: [q 128][k 128][v 128][skip 128][p0 96][p1 96][pad 64]

// ------------------------- device scratch -------------------------
__device__ __half g_dst[(size_t)NN * 320];           // per-node dst data: q[128], p[192] fp16
__device__ __half g_src[(size_t)NN * 256];           // per-node src data: k[128], v[128] fp16
__device__ __half g_whT[WC * 128];                   // W^T (fp16), [col][k]
__device__ float g_bias[WC];
// sort scratch (SoA sorted edge data)
__device__ int g_cnt[NN];
__device__ int g_off[NN + 1];
__device__ int g_cursor[NN];
__device__ int g_esrc[EE];
__device__ int g_eidx[EE];
__device__ float g_erel[EE];
__device__ int g_bsum[512];

// ------------------------- generic helpers -------------------------
__device__ __forceinline__ unsigned long long pk2(float lo, float hi) {
    unsigned long long r;
    asm("mov.b64 %0, {%1,%2};" : "=l"(r) : "f"(lo), "f"(hi));
    return r;
}
__device__ __forceinline__ float2 upk2(unsigned long long v) {
    float2 r;
    asm("mov.b64 {%0,%1}, %2;" : "=f"(r.x), "=f"(r.y) : "l"(v));
    return r;
}
__device__ __forceinline__ unsigned long long ffma2(unsigned long long a, unsigned long long b,
                                                    unsigned long long c) {
    unsigned long long d;
    asm("fma.rn.f32x2 %0, %1, %2, %3;" : "=l"(d) : "l"(a), "l"(b), "l"(c));
    return d;
}
__device__ __forceinline__ uint32_t smem_u32(const void* p) {
    uint32_t a;
    asm("{ .reg .u64 t; cvta.to.shared.u64 t, %1; cvt.u32.u64 %0, t; }" : "=r"(a) : "l"(p));
    return a;
}
__device__ __forceinline__ void ldsm4(uint32_t* r, uint32_t addr) {
    asm volatile("ldmatrix.sync.aligned.m8n8.x4.shared.b16 {%0,%1,%2,%3}, [%4];"
                 : "=r"(r[0]), "=r"(r[1]), "=r"(r[2]), "=r"(r[3]) : "r"(addr));
}
__device__ __forceinline__ void mma16816(float* c, const uint32_t* a, uint32_t b0, uint32_t b1) {
    asm volatile(
        "mma.sync.aligned.m16n8k16.row.col.f32.f16.f16.f32 "
        "{%0,%1,%2,%3}, {%4,%5,%6,%7}, {%8,%9}, {%0,%1,%2,%3};"
        : "+f"(c[0]), "+f"(c[1]), "+f"(c[2]), "+f"(c[3])
        : "r"(a[0]), "r"(a[1]), "r"(a[2]), "r"(a[3]), "r"(b0), "r"(b1));
}
__device__ __forceinline__ void cp16(uint32_t saddr, const void* g) {
    asm volatile("cp.async.cg.shared.global [%0], [%1], 16;" :: "r"(saddr), "l"(g));
}
#define CP_COMMIT() asm volatile("cp.async.commit_group;" ::: "memory")
#define CP_WAIT1()  asm volatile("cp.async.wait_group 1;" ::: "memory")
#define CP_WAIT0()  asm volatile("cp.async.wait_group 0;" ::: "memory")

// ------------------------- kernel: init sort scratch -------------------------
__global__ void k_init() {
    int i = blockIdx.x * blockDim.x + threadIdx.x;
    if (i < NN) {
        g_cnt[i] = 0;
        g_cursor[i] = 0;
    }
}

// ------------------------- kernel: fused weights (transposed, fp16) ----------
__global__ void k_prep(const float* __restrict__ Wq, const float* __restrict__ bq,
                       const float* __restrict__ Wk, const float* __restrict__ bk,
                       const float* __restrict__ Wv, const float* __restrict__ bv,
                       const float* __restrict__ We,
                       const float* __restrict__ Ws, const float* __restrict__ bs) {
    int i = blockIdx.x;  // 0..127 (input dim k)
    for (int c = threadIdx.x; c < WC; c += blockDim.x) {
        float w = 0.0f, b = 0.0f;
        if (c < 128)      { w = Wq[i * 128 + c];         b = bq[c]; }
        else if (c < 256) { w = Wk[i * 128 + (c - 128)]; b = bk[c - 128]; }
        else if (c < 384) { w = Wv[i * 128 + (c - 256)]; b = bv[c - 256]; }
        else if (c < 512) { w = Ws[i * 128 + (c - 384)]; b = bs[c - 384]; }
        else if (c < 704) {
            int hd = c - 512;
            int h = hd / 96, d = hd % 96;
            float acc = 0.0f, accb = 0.0f;
            #pragma unroll 8
            for (int cc = 0; cc < 64; ++cc) {
                float we = We[d * 128 + h * 64 + cc];
                acc = fmaf(Wq[i * 128 + h * 64 + cc], we, acc);
                accb = fmaf(bq[h * 64 + cc], we, accb);
            }
            w = acc; b = accb;
        }
        g_whT[c * 128 + i] = __float2half_rn(w);
        if (i == 0) g_bias[c] = b;
    }
}

// ------------------------- kernel: HMMA node GEMM (fp16 single-term) ---------
#define A_ROWS 64
#define A_STRIDE 136
#define B_STRIDE 72
#define SZ_A (A_ROWS * A_STRIDE * 2)      // 17408 (single fp16 A)
#define SZ_B (128 * B_STRIDE * 2)         // 18432 per buffer
#define SM_A    0
#define SM_B    (SZ_A)                    // 2 buffers
#define SM_BIAS (SZ_A + 2 * SZ_B)         // 54272
#define SM_TOT  (SM_BIAS + WC * 4)        // 57344

__device__ __forceinline__ void load_B_async(uint32_t sb, int s, int tid) {
    const int chunk = s >> 1, kh = s & 1;
    const uint32_t bbase = SM_B + (uint32_t)(s & 1) * SZ_B;
    for (int i = tid; i < 128 * 8; i += 256) {
        int c = i >> 3, seg = i & 7;
        size_t gsrc = (size_t)(chunk * 128 + c) * 128 + kh * 64 + seg * 8;
        uint32_t doff = (uint32_t)(c * (B_STRIDE * 2) + seg * 16);
        cp16(sb + bbase + doff, g_whT + gsrc);
    }
}

__global__ void __launch_bounds__(256, 3) k_gemm_mma(const float* __restrict__ x,
                                                     float* __restrict__ out) {
    extern __shared__ char smem[];
    const uint32_t sb = smem_u32(smem);
    const int tid = threadIdx.x, wid = tid >> 5, lane = tid & 31;
    const int row0 = blockIdx.x * A_ROWS;

    load_B_async(sb, 0, tid);
    CP_COMMIT();

    float* sbias = (float*)(smem + SM_BIAS);
    for (int i = tid; i < WC; i += 256) sbias[i] = g_bias[i];

    // load A tile [64x128] as single fp16
    for (int i = tid; i < A_ROWS * 32; i += 256) {
        int r = i >> 5, k4 = (i & 31) << 2;
        int row = row0 + r;
        float4 v = (row < NN) ? __ldcs((const float4*)(x + (size_t)row * 128 + k4))
                              : make_float4(0.f, 0.f, 0.f, 0.f);
        __half2 h01 = __floats2half2_rn(v.x, v.y);
        __half2 h23 = __floats2half2_rn(v.z, v.w);
        uint32_t off = (uint32_t)(r * (A_STRIDE * 2) + k4 * 2);
        *(uint2*)(smem + SM_A + off) = make_uint2(*(uint32_t*)&h01, *(uint32_t*)&h23);
    }

    const int wm = wid & 1, wn = wid >> 1;       // warp grid 2 x 4
    const int rw = wm * 32, cw = wn * 32;        // warp tile 32 x 32
    const uint32_t a_off = (uint32_t)((rw + (lane & 15)) * (A_STRIDE * 2) + (lane >> 4) * 16);
    const uint32_t b_off = (uint32_t)((cw + (lane & 15)) * (B_STRIDE * 2) + (lane >> 4) * 16);
    const int trow = lane >> 2;
    const int tcol = (lane & 3) * 2;

    float acc[2][4][4];

    for (int s = 0; s < 12; ++s) {
        const int chunk = s >> 1, kh = s & 1;
        if (kh == 0) {
            #pragma unroll
            for (int i = 0; i < 2; ++i)
                #pragma unroll
                for (int j = 0; j < 4; ++j)
                    #pragma unroll
                    for (int q = 0; q < 4; ++q) acc[i][j][q] = 0.0f;
        }
        if (s + 1 < 12) {
            load_B_async(sb, s + 1, tid);
            CP_COMMIT();
            CP_WAIT1();
        } else {
            CP_WAIT0();
        }
        __syncthreads();

        const uint32_t sA = sb + SM_A + kh * 128;
        const uint32_t sBh = sb + SM_B + (uint32_t)(s & 1) * SZ_B;
        #pragma unroll
        for (int ks = 0; ks < 4; ++ks) {
            uint32_t a[2][4], bh[2][4];
            #pragma unroll
            for (int i = 0; i < 2; ++i)
                ldsm4(a[i], sA + a_off + i * (16 * A_STRIDE * 2) + ks * 32);
            #pragma unroll
            for (int j16 = 0; j16 < 2; ++j16)
                ldsm4(bh[j16], sBh + b_off + j16 * (16 * B_STRIDE * 2) + ks * 32);
            #pragma unroll
            for (int i = 0; i < 2; ++i) {
                mma16816(acc[i][0], a[i], bh[0][0], bh[0][2]);
                mma16816(acc[i][1], a[i], bh[0][1], bh[0][3]);
                mma16816(acc[i][2], a[i], bh[1][0], bh[1][2]);
                mma16816(acc[i][3], a[i], bh[1][1], bh[1][3]);
            }
        }
        __syncthreads();

        if (kh == 1) {
            if (chunk == 3) {
                // skip -> out (fp32)
                #pragma unroll
                for (int i = 0; i < 2; ++i) {
                    int r = row0 + rw + i * 16 + trow;
                    #pragma unroll
                    for (int j = 0; j < 4; ++j) {
                        int G = 384 + cw + j * 8 + tcol;
                        float b0 = sbias[G], b1 = sbias[G + 1];
                        if (r < NN) {
                            float2 v = make_float2(acc[i][j][0] + b0, acc[i][j][1] + b1);
                            __stcs((float2*)(out + (size_t)r * 128 + (G - 384)), v);
                        }
                        if (r + 8 < NN) {
                            float2 v = make_float2(acc[i][j][2] + b0, acc[i][j][3] + b1);
                            __stcs((float2*)(out + (size_t)(r + 8) * 128 + (G - 384)), v);
                        }
                    }
                }
            } else {
                // q/p -> g_dst fp16, k/v -> g_src fp16
                __half* bp; int stride, sub;
                bool is_kv = (chunk == 1 || chunk == 2);
                if (chunk == 0)      { bp = g_dst; stride = 320; sub = 0;   }
                else if (is_kv)      { bp = g_src; stride = 256; sub = 128; }
                else                 { bp = g_dst; stride = 320; sub = 384; }
                #pragma unroll
                for (int i = 0; i < 2; ++i) {
                    int r = row0 + rw + i * 16 + trow;
                    #pragma unroll
                    for (int j = 0; j < 4; ++j) {
                        int G = chunk * 128 + cw + j * 8 + tcol;
                        if (G >= 704) continue;
                        float b0 = sbias[G], b1 = sbias[G + 1];
                        if (r < NN) {
                            __half2 hv = __floats2half2_rn(acc[i][j][0] + b0,
                                                           acc[i][j][1] + b1);
                            *(__half2*)(bp + (size_t)r * stride + (G - sub)) = hv;
                        }
                        if (r + 8 < NN) {
                            __half2 hv = __floats2half2_rn(acc[i][j][2] + b0,
                                                           acc[i][j][3] + b1);
                            *(__half2*)(bp + (size_t)(r + 8) * stride + (G - sub)) = hv;
                        }
                    }
                }
            }
        }
    }
}

// ------------------------- sort: histogram, scan, permute -------------------------
__global__ void k_hist(const int* __restrict__ ei) {
    int i = blockIdx.x * blockDim.x + threadIdx.x;
    if (i < EE) atomicAdd(&g_cnt[__ldcs(ei + EE + i)], 1);
}

__global__ void k_scan_a() {
    __shared__ int sm[256];
    int t = threadIdx.x;
    int gid = blockIdx.x * 256 + t;
    int val = (gid < NN) ? g_cnt[gid] : 0;
    sm[t] = val;
    __syncthreads();
    #pragma unroll
    for (int o = 1; o < 256; o <<= 1) {
        int add = (t >= o) ? sm[t - o] : 0;
        __syncthreads();
        sm[t] += add;
        __syncthreads();
    }
    if (gid < NN) g_off[gid] = sm[t] - val;
    if (t == 255) g_bsum[blockIdx.x] = sm[255];
}

__global__ void k_scan_b(int nblk) {
    __shared__ int sm[512];
    int t = threadIdx.x;
    int val = (t < nblk) ? g_bsum[t] : 0;
    sm[t] = val;
    __syncthreads();
    #pragma unroll
    for (int o = 1; o < 512; o <<= 1) {
        int add = (t >= o) ? sm[t - o] : 0;
        __syncthreads();
        sm[t] += add;
        __syncthreads();
    }
    if (t < nblk) g_bsum[t] = sm[t] - val;
}

__global__ void k_scan_c() {
    int gid = blockIdx.x * 256 + threadIdx.x;
    if (gid < NN) g_off[gid] += g_bsum[blockIdx.x];
    if (gid == 0) g_off[NN] = EE;
}

__global__ void k_permute(const int* __restrict__ ei, const float* __restrict__ lu,
                          const float* __restrict__ tv) {
    int i = blockIdx.x * blockDim.x + threadIdx.x;
    if (i >= EE) return;
    int d = __ldcs(ei + EE + i);
    int s = __ldcs(ei + i);
    int pos = g_off[d] + atomicAdd(&g_cursor[d], 1);
    g_esrc[pos] = s;
    g_eidx[pos] = i;
    g_erel[pos] = lu[s] - __ldcs(tv + i);
}

// ------------------------- kernel: fused edge pass + s@We epilogue -------------
// Persistent single-wave grid (148*3 CTAs). SoA prefetched one batch ahead so
// k/v gather addresses are ready at iteration start (shorter dependency chain).
#define EDGE_CTAS 444
#define EDGE_WARPS (EDGE_CTAS * 8)
#define SM_EDGE ((96 * 128 + 8 * 192) * 4)   // We fp32 + per-warp s: 55296 B

__global__ void __launch_bounds__(256, 3) k_edge(const float* __restrict__ msg,
                                                 const float* __restrict__ time_w,
                                                 const float* __restrict__ time_b,
                                                 const float* __restrict__ We,
                                                 float* __restrict__ out) {
    extern __shared__ float sme[];
    float* sWe = sme;                     // [96][128]
    const int tid = threadIdx.x, wid = tid >> 5, lane = tid & 31;

    for (int i = tid; i < 96 * 128 / 4; i += 256)
        ((float4*)sWe)[i] = ((const float4*)We)[i];
    __syncthreads();

    float* sS = sme + 96 * 128 + wid * 192;   // per-warp s[d][h]
    const float tww = time_w[lane], tbb = time_b[lane];
    const bool h0lane = (lane < 16);
    const int hsel = h0lane ? 0 : 1;

    for (int n = blockIdx.x * 8 + wid; n < NN; n += EDGE_WARPS) {
        const int off0 = g_off[n];
        const int deg = g_off[n + 1] - off0;
        if (deg == 0) continue;   // out already holds skip

        const __half* dp = g_dst + (size_t)n * 320;
        uint2 qr = __ldcs((const uint2*)(dp + lane * 4));
        const __half2 qh01 = *(const __half2*)&qr.x;
        const __half2 qh23 = *(const __half2*)&qr.y;
        short ps0 = __ldcs((const short*)(dp + 128 + lane));
        short ps1 = __ldcs((const short*)(dp + 160 + lane));
        short ps2 = __ldcs((const short*)(dp + 192 + lane));
        short ps3 = __ldcs((const short*)(dp + 224 + lane));
        short ps4 = __ldcs((const short*)(dp + 256 + lane));
        short ps5 = __ldcs((const short*)(dp + 288 + lane));
        const float p00 = __half2float(*(__half*)&ps0), p01 = __half2float(*(__half*)&ps1);
        const float p02 = __half2float(*(__half*)&ps2), p10 = __half2float(*(__half*)&ps3);
        const float p11 = __half2float(*(__half*)&ps4), p12 = __half2float(*(__half*)&ps5);

        float den0 = 0.f, den1 = 0.f;
        float4 aco = make_float4(0.f, 0.f, 0.f, 0.f);
        float2 as0 = make_float2(0.f, 0.f), as1 = as0, as2 = as0;

        // prefetch SoA for batch 0
        int srcN[4], idxN[4];
        float relN[4];
        #pragma unroll
        for (int j = 0; j < 4; ++j) {
            int pos = off0 + ((j < deg) ? j : 0);
            srcN[j] = __ldcs(g_esrc + pos);
            idxN[j] = __ldcs(g_eidx + pos);
            relN[j] = __ldcs(g_erel + pos);
        }

        for (int eb = 0; eb < deg; eb += 4) {
            const int nb = deg - eb;
            float relj[4], ea0[4], ea1[4], ea2[4], u0[4], u1[4];
            uint2 kr[4], vr[4];
            // issue gathers immediately (addresses already resident)
            #pragma unroll
            for (int j = 0; j < 4; ++j) {
                relj[j] = relN[j];
                const __half* sp = g_src + (size_t)srcN[j] * 256;
                kr[j] = *(const uint2*)(sp + lane * 4);        // cached: reused ~8x
                vr[j] = *(const uint2*)(sp + 128 + lane * 4);
                ea1[j] = __ldcs(msg + (size_t)idxN[j] * 64 + lane);
                ea2[j] = __ldcs(msg + (size_t)idxN[j] * 64 + 32 + lane);
            }
            // prefetch SoA for next batch (overlaps with compute below)
            if (eb + 4 < deg) {
                #pragma unroll
                for (int j = 0; j < 4; ++j) {
                    int o = eb + 4 + j;
                    int pos = off0 + ((o < deg) ? o : deg - 1);
                    srcN[j] = __ldcs(g_esrc + pos);
                    idxN[j] = __ldcs(g_eidx + pos);
                    relN[j] = __ldcs(g_erel + pos);
                }
            }

            #pragma unroll
            for (int j = 0; j < 4; ++j) {
                // half2 dot: q . k over this lane's 4 channels
                __half2 t = __hmul2(qh01, *(const __half2*)&kr[j].x);
                t = __hfma2(qh23, *(const __half2*)&kr[j].y, t);
                float2 tf = __half22float2(t);
                float qk = tf.x + tf.y;
                ea0[j] = cosf(fmaf(relj[j], tww, tbb));
                u0[j] = ea0[j] * p00 + ea1[j] * p01 + ea2[j] * p02 + (h0lane ? qk : 0.f);
                u1[j] = ea0[j] * p10 + ea1[j] * p11 + ea2[j] * p12 + (h0lane ? 0.f : qk);
            }
            // joint reduction: one o=16 step on all 8, fold into w (own head per
            // half-warp), 4 steps within halves, final exchange for other head.
            float w[4], oth[4];
            #pragma unroll
            for (int j = 0; j < 4; ++j) {
                u0[j] += __shfl_xor_sync(0xffffffffu, u0[j], 16);
                u1[j] += __shfl_xor_sync(0xffffffffu, u1[j], 16);
                w[j] = h0lane ? u0[j] : u1[j];
            }
            #pragma unroll
            for (int o = 8; o; o >>= 1) {
                #pragma unroll
                for (int j = 0; j < 4; ++j)
                    w[j] += __shfl_xor_sync(0xffffffffu, w[j], o);
            }
            #pragma unroll
            for (int j = 0; j < 4; ++j)
                oth[j] = __shfl_xor_sync(0xffffffffu, w[j], 16);

            #pragma unroll
            for (int j = 0; j < 4; ++j) {
                if (j < nb) {
                    float eo = __expf(w[j] * 0.125f);     // own head's exp
                    float ex = __expf(oth[j] * 0.125f);   // other head's exp
                    float e0 = h0lane ? eo : ex;
                    float e1 = h0lane ? ex : eo;
                    den0 += e0; den1 += e1;
                    float2 va = __half22float2(*(const __half2*)&vr[j].x);
                    float2 vb = __half22float2(*(const __half2*)&vr[j].y);
                    aco.x = fmaf(va.x, eo, aco.x);
                    aco.y = fmaf(va.y, eo, aco.y);
                    aco.z = fmaf(vb.x, eo, aco.z);
                    aco.w = fmaf(vb.y, eo, aco.w);
                    as0.x = fmaf(ea0[j], e0, as0.x);  as0.y = fmaf(ea0[j], e1, as0.y);
                    as1.x = fmaf(ea1[j], e0, as1.x);  as1.y = fmaf(ea1[j], e1, as1.y);
                    as2.x = fmaf(ea2[j], e0, as2.x);  as2.y = fmaf(ea2[j], e1, as2.y);
                }
            }
        }

        float i0 = 1.0f / (den0 + 1e-16f);
        float i1 = 1.0f / (den1 + 1e-16f);

        // stage normalized s into per-warp smem: sS[d*2 + h]
        sS[lane * 2 + 0]        = as0.x * i0;  sS[lane * 2 + 1]        = as0.y * i1;
        sS[(lane + 32) * 2 + 0] = as1.x * i0;  sS[(lane + 32) * 2 + 1] = as1.y * i1;
        sS[(lane + 64) * 2 + 0] = as2.x * i0;  sS[(lane + 64) * 2 + 1] = as2.y * i1;
        __syncwarp();

        // matvec: r[c] = sum_d s[d][h(c)] * We[d][c], cols c = lane*4..lane*4+3
        unsigned long long a01 = 0ULL, a23 = 0ULL;
        const float4* w4 = (const float4*)sWe + lane;
        #pragma unroll 8
        for (int d = 0; d < 96; ++d) {
            float sv = sS[d * 2 + hsel];
            float4 w = w4[d * 32];
            unsigned long long svp = pk2(sv, sv);
            a01 = ffma2(pk2(w.x, w.y), svp, a01);
            a23 = ffma2(pk2(w.z, w.w), svp, a23);
        }
        __syncwarp();
        float2 r01 = upk2(a01), r23 = upk2(a23);

        float ih = h0lane ? i0 : i1;
        float4* op = (float4*)(out + (size_t)n * 128 + lane * 4);
        float4 o4 = __ldcs(op);
        o4.x += aco.x * ih + r01.x;
        o4.y += aco.y * ih + r01.y;
        o4.z += aco.z * ih + r23.x;
        o4.w += aco.w * ih + r23.y;
        __stcs(op, o4);
    }
}

// ------------------------- launch -------------------------
extern "C" void kernel_launch(void* const* d_in, const int* in_sizes, int n_in,
                              void* d_out, int out_size) {
    const float* x   = (const float*)d_in[0];
    const float* lu  = (const float*)d_in[1];
    const float* tv  = (const float*)d_in[2];
    const float* msg = (const float*)d_in[3];
    const int*   ei  = (const int*)d_in[4];
    const float* tw  = (const float*)d_in[5];
    const float* tb  = (const float*)d_in[6];
    const float* Wq  = (const float*)d_in[7];
    const float* bq  = (const float*)d_in[8];
    const float* Wk  = (const float*)d_in[9];
    const float* bk  = (const float*)d_in[10];
    const float* Wv  = (const float*)d_in[11];
    const float* bv  = (const float*)d_in[12];
    const float* We  = (const float*)d_in[13];
    const float* Ws  = (const float*)d_in[14];
    const float* bs  = (const float*)d_in[15];
    float* out = (float*)d_out;

    static cudaStream_t s2 = nullptr;
    static cudaEvent_t evFork = nullptr, evJoin = nullptr;
    if (!s2) {
        cudaFuncSetAttribute(k_gemm_mma, cudaFuncAttributeMaxDynamicSharedMemorySize, SM_TOT);
        cudaFuncSetAttribute(k_edge, cudaFuncAttributeMaxDynamicSharedMemorySize, SM_EDGE);
        cudaStreamCreateWithFlags(&s2, cudaStreamNonBlocking);
        cudaEventCreateWithFlags(&evFork, cudaEventDisableTiming);
        cudaEventCreateWithFlags(&evJoin, cudaEventDisableTiming);
    }

    const int nblk = (NN + 255) / 256;  // 391

    // Fork s2 off the main stream.
    cudaEventRecord(evFork, 0);
    cudaStreamWaitEvent(s2, evFork, 0);

    // Submission order chosen so index 3 = k_gemm_mma (ncu -s5 profiles idx 3).
    k_prep<<<128, 256>>>(Wq, bq, Wk, bk, Wv, bv, We, Ws, bs);         // idx 0 (main)
    k_init<<<nblk, 256, 0, s2>>>();                                   // idx 1 (s2)
    k_hist<<<(EE + 255) / 256, 256, 0, s2>>>(ei);                     // idx 2 (s2)
    k_gemm_mma<<<(NN + A_ROWS - 1) / A_ROWS, 256, SM_TOT>>>(x, out);  // idx 3 (main)
    k_scan_a<<<nblk, 256, 0, s2>>>();                                 // idx 4
    k_scan_b<<<1, 512, 0, s2>>>(nblk);                                // idx 5
    k_scan_c<<<nblk, 256, 0, s2>>>();                                 // idx 6
    k_permute<<<(EE + 255) / 256, 256, 0, s2>>>(ei, lu, tv);          // idx 7
    cudaEventRecord(evJoin, s2);

    // Join, then fused edge pass (attn + skip + s@We epilogue).
    cudaStreamWaitEvent(0, evJoin, 0);
    k_edge<<<EDGE_CTAS, 256, SM_EDGE>>>(msg, tw, tb, We, out);        // idx 8
}

// round 15
// speedup vs baseline: 1.3221x; 1.0424x over previous
#include <cuda_runtime.h>
#include <cuda_fp16.h>
#include <math_constants.h>
#include <cstdint>

// Problem constants (fixed shapes)
#define NN 100000
#define EE 800000
#define WC 768   // fused weight cols: [q 128][k 128][v 128][skip 128][p0 96][p1 96][pad 64]

// ------------------------- device scratch -------------------------
__device__ __half g_dst[(size_t)NN * 320];           // per-node dst data: q[128], p[192] fp16
__device__ __half g_src[(size_t)NN * 256];           // per-node src data: k[128], v[128] fp16
__device__ __half g_whT[WC * 128];                   // W^T (fp16), [col][k]
__device__ float g_bias[WC];
// sort scratch (SoA sorted edge data)
__device__ int g_cnt[NN];
__device__ int g_off[NN + 1];
__device__ int g_cursor[NN];
__device__ int g_esrc[EE];
__device__ int g_eidx[EE];
__device__ float g_erel[EE];
__device__ int g_bsum[512];

// ------------------------- generic helpers -------------------------
__device__ __forceinline__ unsigned long long pk2(float lo, float hi) {
    unsigned long long r;
    asm("mov.b64 %0, {%1,%2};" : "=l"(r) : "f"(lo), "f"(hi));
    return r;
}
__device__ __forceinline__ float2 upk2(unsigned long long v) {
    float2 r;
    asm("mov.b64 {%0,%1}, %2;" : "=f"(r.x), "=f"(r.y) : "l"(v));
    return r;
}
__device__ __forceinline__ unsigned long long ffma2(unsigned long long a, unsigned long long b,
                                                    unsigned long long c) {
    unsigned long long d;
    asm("fma.rn.f32x2 %0, %1, %2, %3;" : "=l"(d) : "l"(a), "l"(b), "l"(c));
    return d;
}
__device__ __forceinline__ uint32_t smem_u32(const void* p) {
    uint32_t a;
    asm("{ .reg .u64 t; cvta.to.shared.u64 t, %1; cvt.u32.u64 %0, t; }" : "=r"(a) : "l"(p));
    return a;
}
__device__ __forceinline__ void ldsm4(uint32_t* r, uint32_t addr) {
    asm volatile("ldmatrix.sync.aligned.m8n8.x4.shared.b16 {%0,%1,%2,%3}, [%4];"
                 : "=r"(r[0]), "=r"(r[1]), "=r"(r[2]), "=r"(r[3]) : "r"(addr));
}
__device__ __forceinline__ void mma16816(float* c, const uint32_t* a, uint32_t b0, uint32_t b1) {
    asm volatile(
        "mma.sync.aligned.m16n8k16.row.col.f32.f16.f16.f32 "
        "{%0,%1,%2,%3}, {%4,%5,%6,%7}, {%8,%9}, {%0,%1,%2,%3};"
        : "+f"(c[0]), "+f"(c[1]), "+f"(c[2]), "+f"(c[3])
        : "r"(a[0]), "r"(a[1]), "r"(a[2]), "r"(a[3]), "r"(b0), "r"(b1));
}
__device__ __forceinline__ void cp16(uint32_t saddr, const void* g) {
    asm volatile("cp.async.cg.shared.global [%0], [%1], 16;" :: "r"(saddr), "l"(g));
}
#define CP_COMMIT() asm volatile("cp.async.commit_group;" ::: "memory")
#define CP_WAIT1()  asm volatile("cp.async.wait_group 1;" ::: "memory")
#define CP_WAIT0()  asm volatile("cp.async.wait_group 0;" ::: "memory")

// ------------------------- kernel: init sort scratch -------------------------
__global__ void k_init() {
    int i = blockIdx.x * blockDim.x + threadIdx.x;
    if (i < NN) {
        g_cnt[i] = 0;
        g_cursor[i] = 0;
    }
}

// ------------------------- kernel: fused weights (transposed, fp16) ----------
__global__ void k_prep(const float* __restrict__ Wq, const float* __restrict__ bq,
                       const float* __restrict__ Wk, const float* __restrict__ bk,
                       const float* __restrict__ Wv, const float* __restrict__ bv,
                       const float* __restrict__ We,
                       const float* __restrict__ Ws, const float* __restrict__ bs) {
    int i = blockIdx.x;  // 0..127 (input dim k)
    for (int c = threadIdx.x; c < WC; c += blockDim.x) {
        float w = 0.0f, b = 0.0f;
        if (c < 128)      { w = Wq[i * 128 + c];         b = bq[c]; }
        else if (c < 256) { w = Wk[i * 128 + (c - 128)]; b = bk[c - 128]; }
        else if (c < 384) { w = Wv[i * 128 + (c - 256)]; b = bv[c - 256]; }
        else if (c < 512) { w = Ws[i * 128 + (c - 384)]; b = bs[c - 384]; }
        else if (c < 704) {
            int hd = c - 512;
            int h = hd / 96, d = hd % 96;
            float acc = 0.0f, accb = 0.0f;
            #pragma unroll 8
            for (int cc = 0; cc < 64; ++cc) {
                float we = We[d * 128 + h * 64 + cc];
                acc = fmaf(Wq[i * 128 + h * 64 + cc], we, acc);
                accb = fmaf(bq[h * 64 + cc], we, accb);
            }
            w = acc; b = accb;
        }
        g_whT[c * 128 + i] = __float2half_rn(w);
        if (i == 0) g_bias[c] = b;
    }
}

// ------------------------- kernel: HMMA node GEMM (fp16 single-term) ---------
#define A_ROWS 64
#define A_STRIDE 136
#define B_STRIDE 72
#define SZ_A (A_ROWS * A_STRIDE * 2)      // 17408 (single fp16 A)
#define SZ_B (128 * B_STRIDE * 2)         // 18432 per buffer
#define SM_A    0
#define SM_B    (SZ_A)                    // 2 buffers
#define SM_BIAS (SZ_A + 2 * SZ_B)         // 54272
#define SM_TOT  (SM_BIAS + WC * 4)        // 57344

__device__ __forceinline__ void load_B_async(uint32_t sb, int s, int tid) {
    const int chunk = s >> 1, kh = s & 1;
    const uint32_t bbase = SM_B + (uint32_t)(s & 1) * SZ_B;
    for (int i = tid; i < 128 * 8; i += 256) {
        int c = i >> 3, seg = i & 7;
        size_t gsrc = (size_t)(chunk * 128 + c) * 128 + kh * 64 + seg * 8;
        uint32_t doff = (uint32_t)(c * (B_STRIDE * 2) + seg * 16);
        cp16(sb + bbase + doff, g_whT + gsrc);
    }
}

__global__ void __launch_bounds__(256, 3) k_gemm_mma(const float* __restrict__ x,
                                                     float* __restrict__ out) {
    extern __shared__ char smem[];
    const uint32_t sb = smem_u32(smem);
    const int tid = threadIdx.x, wid = tid >> 5, lane = tid & 31;
    const int row0 = blockIdx.x * A_ROWS;

    load_B_async(sb, 0, tid);
    CP_COMMIT();

    float* sbias = (float*)(smem + SM_BIAS);
    for (int i = tid; i < WC; i += 256) sbias[i] = g_bias[i];

    // load A tile [64x128] as single fp16
    for (int i = tid; i < A_ROWS * 32; i += 256) {
        int r = i >> 5, k4 = (i & 31) << 2;
        int row = row0 + r;
        float4 v = (row < NN) ? __ldcs((const float4*)(x + (size_t)row * 128 + k4))
                              : make_float4(0.f, 0.f, 0.f, 0.f);
        __half2 h01 = __floats2half2_rn(v.x, v.y);
        __half2 h23 = __floats2half2_rn(v.z, v.w);
        uint32_t off = (uint32_t)(r * (A_STRIDE * 2) + k4 * 2);
        *(uint2*)(smem + SM_A + off) = make_uint2(*(uint32_t*)&h01, *(uint32_t*)&h23);
    }

    const int wm = wid & 1, wn = wid >> 1;       // warp grid 2 x 4
    const int rw = wm * 32, cw = wn * 32;        // warp tile 32 x 32
    const uint32_t a_off = (uint32_t)((rw + (lane & 15)) * (A_STRIDE * 2) + (lane >> 4) * 16);
    const uint32_t b_off = (uint32_t)((cw + (lane & 15)) * (B_STRIDE * 2) + (lane >> 4) * 16);
    const int trow = lane >> 2;
    const int tcol = (lane & 3) * 2;

    float acc[2][4][4];

    for (int s = 0; s < 12; ++s) {
        const int chunk = s >> 1, kh = s & 1;
        if (kh == 0) {
            #pragma unroll
            for (int i = 0; i < 2; ++i)
                #pragma unroll
                for (int j = 0; j < 4; ++j)
                    #pragma unroll
                    for (int q = 0; q < 4; ++q) acc[i][j][q] = 0.0f;
        }
        if (s + 1 < 12) {
            load_B_async(sb, s + 1, tid);
            CP_COMMIT();
            CP_WAIT1();
        } else {
            CP_WAIT0();
        }
        __syncthreads();

        const uint32_t sA = sb + SM_A + kh * 128;
        const uint32_t sBh = sb + SM_B + (uint32_t)(s & 1) * SZ_B;
        #pragma unroll
        for (int ks = 0; ks < 4; ++ks) {
            uint32_t a[2][4], bh[2][4];
            #pragma unroll
            for (int i = 0; i < 2; ++i)
                ldsm4(a[i], sA + a_off + i * (16 * A_STRIDE * 2) + ks * 32);
            #pragma unroll
            for (int j16 = 0; j16 < 2; ++j16)
                ldsm4(bh[j16], sBh + b_off + j16 * (16 * B_STRIDE * 2) + ks * 32);
            #pragma unroll
            for (int i = 0; i < 2; ++i) {
                mma16816(acc[i][0], a[i], bh[0][0], bh[0][2]);
                mma16816(acc[i][1], a[i], bh[0][1], bh[0][3]);
                mma16816(acc[i][2], a[i], bh[1][0], bh[1][2]);
                mma16816(acc[i][3], a[i], bh[1][1], bh[1][3]);
            }
        }
        __syncthreads();

        if (kh == 1) {
            if (chunk == 3) {
                // skip -> out (fp32)
                #pragma unroll
                for (int i = 0; i < 2; ++i) {
                    int r = row0 + rw + i * 16 + trow;
                    #pragma unroll
                    for (int j = 0; j < 4; ++j) {
                        int G = 384 + cw + j * 8 + tcol;
                        float b0 = sbias[G], b1 = sbias[G + 1];
                        if (r < NN) {
                            float2 v = make_float2(acc[i][j][0] + b0, acc[i][j][1] + b1);
                            __stcs((float2*)(out + (size_t)r * 128 + (G - 384)), v);
                        }
                        if (r + 8 < NN) {
                            float2 v = make_float2(acc[i][j][2] + b0, acc[i][j][3] + b1);
                            __stcs((float2*)(out + (size_t)(r + 8) * 128 + (G - 384)), v);
                        }
                    }
                }
            } else {
                // q/p -> g_dst fp16, k/v -> g_src fp16
                __half* bp; int stride, sub;
                bool is_kv = (chunk == 1 || chunk == 2);
                if (chunk == 0)      { bp = g_dst; stride = 320; sub = 0;   }
                else if (is_kv)      { bp = g_src; stride = 256; sub = 128; }
                else                 { bp = g_dst; stride = 320; sub = 384; }
                #pragma unroll
                for (int i = 0; i < 2; ++i) {
                    int r = row0 + rw + i * 16 + trow;
                    #pragma unroll
                    for (int j = 0; j < 4; ++j) {
                        int G = chunk * 128 + cw + j * 8 + tcol;
                        if (G >= 704) continue;
                        float b0 = sbias[G], b1 = sbias[G + 1];
                        if (r < NN) {
                            __half2 hv = __floats2half2_rn(acc[i][j][0] + b0,
                                                           acc[i][j][1] + b1);
                            *(__half2*)(bp + (size_t)r * stride + (G - sub)) = hv;
                        }
                        if (r + 8 < NN) {
                            __half2 hv = __floats2half2_rn(acc[i][j][2] + b0,
                                                           acc[i][j][3] + b1);
                            *(__half2*)(bp + (size_t)(r + 8) * stride + (G - sub)) = hv;
                        }
                    }
                }
            }
        }
    }
}

// ------------------------- sort: histogram, scan, permute -------------------------
__global__ void k_hist(const int* __restrict__ ei) {
    int i = blockIdx.x * blockDim.x + threadIdx.x;
    if (i < EE) atomicAdd(&g_cnt[__ldcs(ei + EE + i)], 1);
}

__global__ void k_scan_a() {
    __shared__ int sm[256];
    int t = threadIdx.x;
    int gid = blockIdx.x * 256 + t;
    int val = (gid < NN) ? g_cnt[gid] : 0;
    sm[t] = val;
    __syncthreads();
    #pragma unroll
    for (int o = 1; o < 256; o <<= 1) {
        int add = (t >= o) ? sm[t - o] : 0;
        __syncthreads();
        sm[t] += add;
        __syncthreads();
    }
    if (gid < NN) g_off[gid] = sm[t] - val;
    if (t == 255) g_bsum[blockIdx.x] = sm[255];
}

__global__ void k_scan_b(int nblk) {
    __shared__ int sm[512];
    int t = threadIdx.x;
    int val = (t < nblk) ? g_bsum[t] : 0;
    sm[t] = val;
    __syncthreads();
    #pragma unroll
    for (int o = 1; o < 512; o <<= 1) {
        int add = (t >= o) ? sm[t - o] : 0;
        __syncthreads();
        sm[t] += add;
        __syncthreads();
    }
    if (t < nblk) g_bsum[t] = sm[t] - val;
}

__global__ void k_scan_c() {
    int gid = blockIdx.x * 256 + threadIdx.x;
    if (gid < NN) g_off[gid] += g_bsum[blockIdx.x];
    if (gid == 0) g_off[NN] = EE;
}

__global__ void k_permute(const int* __restrict__ ei, const float* __restrict__ lu,
                          const float* __restrict__ tv) {
    int i = blockIdx.x * blockDim.x + threadIdx.x;
    if (i >= EE) return;
    int d = __ldcs(ei + EE + i);
    int s = __ldcs(ei + i);
    int pos = g_off[d] + atomicAdd(&g_cursor[d], 1);
    g_esrc[pos] = s;
    g_eidx[pos] = i;
    g_erel[pos] = lu[s] - __ldcs(tv + i);
}

// ------------------------- kernel: fused edge pass + s@We epilogue -------------
// Persistent single-wave grid (148*4 CTAs, 32 warps/SM). We in smem as fp16
// (30KB total -> 4 CTAs/SM). launch_bounds(256,4) caps regs at 64.
#define EDGE_CTAS 592
#define EDGE_WARPS (EDGE_CTAS * 8)
#define SM_WE_H (96 * 128 * 2)                  // 24576 B fp16 We
#define SM_EDGE (SM_WE_H + 8 * 192 * 4)         // + per-warp s fp32: 30720 B

__global__ void __launch_bounds__(256, 4) k_edge(const float* __restrict__ msg,
                                                 const float* __restrict__ time_w,
                                                 const float* __restrict__ time_b,
                                                 const float* __restrict__ We,
                                                 float* __restrict__ out) {
    extern __shared__ float sme[];
    __half* sWe = (__half*)sme;               // [96][128] fp16
    const int tid = threadIdx.x, wid = tid >> 5, lane = tid & 31;

    for (int i = tid; i < 96 * 128 / 4; i += 256) {
        float4 w = ((const float4*)We)[i];
        __half2 a = __floats2half2_rn(w.x, w.y);
        __half2 b = __floats2half2_rn(w.z, w.w);
        ((uint2*)sWe)[i] = make_uint2(*(uint32_t*)&a, *(uint32_t*)&b);
    }
    __syncthreads();

    float* sS = (float*)((char*)sme + SM_WE_H) + wid * 192;   // per-warp s[d][h]
    const float tww = time_w[lane], tbb = time_b[lane];
    const bool h0lane = (lane < 16);
    const int hsel = h0lane ? 0 : 1;

    for (int n = blockIdx.x * 8 + wid; n < NN; n += EDGE_WARPS) {
        const int off0 = g_off[n];
        const int deg = g_off[n + 1] - off0;
        if (deg == 0) continue;   // out already holds skip

        const __half* dp = g_dst + (size_t)n * 320;
        uint2 qr = __ldcs((const uint2*)(dp + lane * 4));
        const __half2 qh01 = *(const __half2*)&qr.x;
        const __half2 qh23 = *(const __half2*)&qr.y;
        short ps0 = __ldcs((const short*)(dp + 128 + lane));
        short ps1 = __ldcs((const short*)(dp + 160 + lane));
        short ps2 = __ldcs((const short*)(dp + 192 + lane));
        short ps3 = __ldcs((const short*)(dp + 224 + lane));
        short ps4 = __ldcs((const short*)(dp + 256 + lane));
        short ps5 = __ldcs((const short*)(dp + 288 + lane));
        const float p00 = __half2float(*(__half*)&ps0), p01 = __half2float(*(__half*)&ps1);
        const float p02 = __half2float(*(__half*)&ps2), p10 = __half2float(*(__half*)&ps3);
        const float p11 = __half2float(*(__half*)&ps4), p12 = __half2float(*(__half*)&ps5);

        float den0 = 0.f, den1 = 0.f;
        float4 aco = make_float4(0.f, 0.f, 0.f, 0.f);
        float2 as0 = make_float2(0.f, 0.f), as1 = as0, as2 = as0;

        for (int eb = 0; eb < deg; eb += 4) {
            const int nb = deg - eb;
            int idxj[4];
            float relj[4], ea0[4], ea1[4], ea2[4], u0[4], u1[4];
            uint2 kr[4], vr[4];
            #pragma unroll
            for (int j = 0; j < 4; ++j) {
                int pos = off0 + eb + ((j < nb) ? j : 0);
                int src = __ldcs(g_esrc + pos);
                idxj[j] = __ldcs(g_eidx + pos);
                relj[j] = __ldcs(g_erel + pos);
                const __half* sp = g_src + (size_t)src * 256;
                kr[j] = *(const uint2*)(sp + lane * 4);        // cached: reused ~8x
                vr[j] = *(const uint2*)(sp + 128 + lane * 4);
            }
            #pragma unroll
            for (int j = 0; j < 4; ++j) {
                ea1[j] = __ldcs(msg + (size_t)idxj[j] * 64 + lane);
                ea2[j] = __ldcs(msg + (size_t)idxj[j] * 64 + 32 + lane);
            }
            #pragma unroll
            for (int j = 0; j < 4; ++j) {
                __half2 t = __hmul2(qh01, *(const __half2*)&kr[j].x);
                t = __hfma2(qh23, *(const __half2*)&kr[j].y, t);
                float2 tf = __half22float2(t);
                float qk = tf.x + tf.y;
                ea0[j] = cosf(fmaf(relj[j], tww, tbb));
                u0[j] = ea0[j] * p00 + ea1[j] * p01 + ea2[j] * p02 + (h0lane ? qk : 0.f);
                u1[j] = ea0[j] * p10 + ea1[j] * p11 + ea2[j] * p12 + (h0lane ? 0.f : qk);
            }
            // joint reduction: one o=16 step on all 8, fold into w, 4 steps in
            // halves, final exchange for the other head.
            float w[4], oth[4];
            #pragma unroll
            for (int j = 0; j < 4; ++j) {
                u0[j] += __shfl_xor_sync(0xffffffffu, u0[j], 16);
                u1[j] += __shfl_xor_sync(0xffffffffu, u1[j], 16);
                w[j] = h0lane ? u0[j] : u1[j];
            }
            #pragma unroll
            for (int o = 8; o; o >>= 1) {
                #pragma unroll
                for (int j = 0; j < 4; ++j)
                    w[j] += __shfl_xor_sync(0xffffffffu, w[j], o);
            }
            #pragma unroll
            for (int j = 0; j < 4; ++j)
                oth[j] = __shfl_xor_sync(0xffffffffu, w[j], 16);

            #pragma unroll
            for (int j = 0; j < 4; ++j) {
                if (j < nb) {
                    float eo = __expf(w[j] * 0.125f);
                    float ex = __expf(oth[j] * 0.125f);
                    float e0 = h0lane ? eo : ex;
                    float e1 = h0lane ? ex : eo;
                    den0 += e0; den1 += e1;
                    float2 va = __half22float2(*(const __half2*)&vr[j].x);
                    float2 vb = __half22float2(*(const __half2*)&vr[j].y);
                    aco.x = fmaf(va.x, eo, aco.x);
                    aco.y = fmaf(va.y, eo, aco.y);
                    aco.z = fmaf(vb.x, eo, aco.z);
                    aco.w = fmaf(vb.y, eo, aco.w);
                    as0.x = fmaf(ea0[j], e0, as0.x);  as0.y = fmaf(ea0[j], e1, as0.y);
                    as1.x = fmaf(ea1[j], e0, as1.x);  as1.y = fmaf(ea1[j], e1, as1.y);
                    as2.x = fmaf(ea2[j], e0, as2.x);  as2.y = fmaf(ea2[j], e1, as2.y);
                }
            }
        }

        float i0 = 1.0f / (den0 + 1e-16f);
        float i1 = 1.0f / (den1 + 1e-16f);

        // stage normalized s into per-warp smem: sS[d*2 + h]
        sS[lane * 2 + 0]        = as0.x * i0;  sS[lane * 2 + 1]        = as0.y * i1;
        sS[(lane + 32) * 2 + 0] = as1.x * i0;  sS[(lane + 32) * 2 + 1] = as1.y * i1;
        sS[(lane + 64) * 2 + 0] = as2.x * i0;  sS[(lane + 64) * 2 + 1] = as2.y * i1;
        __syncwarp();

        // matvec: r[c] = sum_d s[d][h(c)] * We[d][c], cols c = lane*4..lane*4+3
        unsigned long long a01 = 0ULL, a23 = 0ULL;
        const uint2* wh = (const uint2*)sWe + lane;   // 4 halves per lane per d
        #pragma unroll 8
        for (int d = 0; d < 96; ++d) {
            float sv = sS[d * 2 + hsel];
            uint2 hw = wh[d * 32];
            float2 w01 = __half22float2(*(const __half2*)&hw.x);
            float2 w23 = __half22float2(*(const __half2*)&hw.y);
            unsigned long long svp = pk2(sv, sv);
            a01 = ffma2(pk2(w01.x, w01.y), svp, a01);
            a23 = ffma2(pk2(w23.x, w23.y), svp, a23);
        }
        __syncwarp();
        float2 r01 = upk2(a01), r23 = upk2(a23);

        float ih = h0lane ? i0 : i1;
        float4* op = (float4*)(out + (size_t)n * 128 + lane * 4);
        float4 o4 = __ldcs(op);
        o4.x += aco.x * ih + r01.x;
        o4.y += aco.y * ih + r01.y;
        o4.z += aco.z * ih + r23.x;
        o4.w += aco.w * ih + r23.y;
        __stcs(op, o4);
    }
}

// ------------------------- launch -------------------------
extern "C" void kernel_launch(void* const* d_in, const int* in_sizes, int n_in,
                              void* d_out, int out_size) {
    const float* x   = (const float*)d_in[0];
    const float* lu  = (const float*)d_in[1];
    const float* tv  = (const float*)d_in[2];
    const float* msg = (const float*)d_in[3];
    const int*   ei  = (const int*)d_in[4];
    const float* tw  = (const float*)d_in[5];
    const float* tb  = (const float*)d_in[6];
    const float* Wq  = (const float*)d_in[7];
    const float* bq  = (const float*)d_in[8];
    const float* Wk  = (const float*)d_in[9];
    const float* bk  = (const float*)d_in[10];
    const float* Wv  = (const float*)d_in[11];
    const float* bv  = (const float*)d_in[12];
    const float* We  = (const float*)d_in[13];
    const float* Ws  = (const float*)d_in[14];
    const float* bs  = (const float*)d_in[15];
    float* out = (float*)d_out;

    static cudaStream_t s2 = nullptr;
    static cudaEvent_t evFork = nullptr, evJoin = nullptr;
    if (!s2) {
        cudaFuncSetAttribute(k_gemm_mma, cudaFuncAttributeMaxDynamicSharedMemorySize, SM_TOT);
        cudaFuncSetAttribute(k_edge, cudaFuncAttributeMaxDynamicSharedMemorySize, SM_EDGE);
        cudaStreamCreateWithFlags(&s2, cudaStreamNonBlocking);
        cudaEventCreateWithFlags(&evFork, cudaEventDisableTiming);
        cudaEventCreateWithFlags(&evJoin, cudaEventDisableTiming);
    }

    const int nblk = (NN + 255) / 256;  // 391

    // Fork s2 off the main stream.
    cudaEventRecord(evFork, 0);
    cudaStreamWaitEvent(s2, evFork, 0);

    // Submission order chosen so index 3 = k_gemm_mma (ncu -s5 profiles idx 3).
    k_prep<<<128, 256>>>(Wq, bq, Wk, bk, Wv, bv, We, Ws, bs);         // idx 0 (main)
    k_init<<<nblk, 256, 0, s2>>>();                                   // idx 1 (s2)
    k_hist<<<(EE + 255) / 256, 256, 0, s2>>>(ei);                     // idx 2 (s2)
    k_gemm_mma<<<(NN + A_ROWS - 1) / A_ROWS, 256, SM_TOT>>>(x, out);  // idx 3 (main)
    k_scan_a<<<nblk, 256, 0, s2>>>();                                 // idx 4
    k_scan_b<<<1, 512, 0, s2>>>(nblk);                                // idx 5
    k_scan_c<<<nblk, 256, 0, s2>>>();                                 // idx 6
    k_permute<<<(EE + 255) / 256, 256, 0, s2>>>(ei, lu, tv);          // idx 7
    cudaEventRecord(evJoin, s2);

    // Join, then fused edge pass (attn + skip + s@We epilogue).
    cudaStreamWaitEvent(0, evJoin, 0);
    k_edge<<<EDGE_CTAS, 256, SM_EDGE>>>(msg, tw, tb, We, out);        // idx 8
}

// round 16
// speedup vs baseline: 1.3346x; 1.0095x over previous
#include <cuda_runtime.h>
#include <cuda_fp16.h>
#include <math_constants.h>
#include <cstdint>

// Problem constants (fixed shapes)
#define NN 100000
#define EE 800000
#define WC 768   // fused weight cols: [q 128][k 128][v 128][skip 128][p0 96][p1 96][pad 64]

// ------------------------- device scratch -------------------------
// g_dst layout per node (fp16): q[0..127], p[128..319], skip[320..447]
__device__ __half g_dst[(size_t)NN * 448];
__device__ __half g_src[(size_t)NN * 256];           // k[128], v[128] fp16
__device__ __half g_whT[WC * 128];                   // W^T (fp16), [col][k]
__device__ float g_bias[WC];
// sort scratch (SoA sorted edge data)
__device__ int g_cnt[NN];
__device__ int g_off[NN + 1];
__device__ int g_cursor[NN];
__device__ int g_esrc[EE];
__device__ int g_eidx[EE];
__device__ float g_erel[EE];
__device__ int g_bsum[512];

// ------------------------- generic helpers -------------------------
__device__ __forceinline__ unsigned long long pk2(float lo, float hi) {
    unsigned long long r;
    asm("mov.b64 %0, {%1,%2};" : "=l"(r) : "f"(lo), "f"(hi));
    return r;
}
__device__ __forceinline__ float2 upk2(unsigned long long v) {
    float2 r;
    asm("mov.b64 {%0,%1}, %2;" : "=f"(r.x), "=f"(r.y) : "l"(v));
    return r;
}
__device__ __forceinline__ unsigned long long ffma2(unsigned long long a, unsigned long long b,
                                                    unsigned long long c) {
    unsigned long long d;
    asm("fma.rn.f32x2 %0, %1, %2, %3;" : "=l"(d) : "l"(a), "l"(b), "l"(c));
    return d;
}
__device__ __forceinline__ uint32_t smem_u32(const void* p) {
    uint32_t a;
    asm("{ .reg .u64 t; cvta.to.shared.u64 t, %1; cvt.u32.u64 %0, t; }" : "=r"(a) : "l"(p));
    return a;
}
__device__ __forceinline__ void ldsm4(uint32_t* r, uint32_t addr) {
    asm volatile("ldmatrix.sync.aligned.m8n8.x4.shared.b16 {%0,%1,%2,%3}, [%4];"
                 : "=r"(r[0]), "=r"(r[1]), "=r"(r[2]), "=r"(r[3]) : "r"(addr));
}
__device__ __forceinline__ void mma16816(float* c, const uint32_t* a, uint32_t b0, uint32_t b1) {
    asm volatile(
        "mma.sync.aligned.m16n8k16.row.col.f32.f16.f16.f32 "
        "{%0,%1,%2,%3}, {%4,%5,%6,%7}, {%8,%9}, {%0,%1,%2,%3};"
        : "+f"(c[0]), "+f"(c[1]), "+f"(c[2]), "+f"(c[3])
        : "r"(a[0]), "r"(a[1]), "r"(a[2]), "r"(a[3]), "r"(b0), "r"(b1));
}
__device__ __forceinline__ void cp16(uint32_t saddr, const void* g) {
    asm volatile("cp.async.cg.shared.global [%0], [%1], 16;" :: "r"(saddr), "l"(g));
}
#define CP_COMMIT() asm volatile("cp.async.commit_group;" ::: "memory")
#define CP_WAIT1()  asm volatile("cp.async.wait_group 1;" ::: "memory")
#define CP_WAIT0()  asm volatile("cp.async.wait_group 0;" ::: "memory")

// ------------------------- kernel: init sort scratch -------------------------
__global__ void k_init() {
    int i = blockIdx.x * blockDim.x + threadIdx.x;
    if (i < NN) {
        g_cnt[i] = 0;
        g_cursor[i] = 0;
    }
}

// ------------------------- kernel: fused weights (transposed, fp16) ----------
__global__ void k_prep(const float* __restrict__ Wq, const float* __restrict__ bq,
                       const float* __restrict__ Wk, const float* __restrict__ bk,
                       const float* __restrict__ Wv, const float* __restrict__ bv,
                       const float* __restrict__ We,
                       const float* __restrict__ Ws, const float* __restrict__ bs) {
    int i = blockIdx.x;  // 0..127 (input dim k)
    for (int c = threadIdx.x; c < WC; c += blockDim.x) {
        float w = 0.0f, b = 0.0f;
        if (c < 128)      { w = Wq[i * 128 + c];         b = bq[c]; }
        else if (c < 256) { w = Wk[i * 128 + (c - 128)]; b = bk[c - 128]; }
        else if (c < 384) { w = Wv[i * 128 + (c - 256)]; b = bv[c - 256]; }
        else if (c < 512) { w = Ws[i * 128 + (c - 384)]; b = bs[c - 384]; }
        else if (c < 704) {
            int hd = c - 512;
            int h = hd / 96, d = hd % 96;
            float acc = 0.0f, accb = 0.0f;
            #pragma unroll 8
            for (int cc = 0; cc < 64; ++cc) {
                float we = We[d * 128 + h * 64 + cc];
                acc = fmaf(Wq[i * 128 + h * 64 + cc], we, acc);
                accb = fmaf(bq[h * 64 + cc], we, accb);
            }
            w = acc; b = accb;
        }
        g_whT[c * 128 + i] = __float2half_rn(w);
        if (i == 0) g_bias[c] = b;
    }
}

// ------------------------- kernel: HMMA node GEMM (fp16, 128-row tiles) ------
// A resident (128x128 fp16), warp tile 32x64 (2x4 warp grid over rows x cols).
// LDSM:MMA = 6:16 per ks step. All outputs fp16 to g_dst / g_src.
#define A_ROWS 128
#define A_STRIDE 136
#define B_STRIDE 72
#define SZ_A (A_ROWS * A_STRIDE * 2)      // 34816
#define SZ_B (128 * B_STRIDE * 2)         // 18432 per buffer
#define SM_A    0
#define SM_B    (SZ_A)                    // 2 buffers
#define SM_BIAS (SZ_A + 2 * SZ_B)         // 71680
#define SM_TOT  (SM_BIAS + WC * 4)        // 74752

__device__ __forceinline__ void load_B_async(uint32_t sb, int s, int tid) {
    const int chunk = s >> 1, kh = s & 1;
    const uint32_t bbase = SM_B + (uint32_t)(s & 1) * SZ_B;
    for (int i = tid; i < 128 * 8; i += 256) {
        int c = i >> 3, seg = i & 7;
        size_t gsrc = (size_t)(chunk * 128 + c) * 128 + kh * 64 + seg * 8;
        uint32_t doff = (uint32_t)(c * (B_STRIDE * 2) + seg * 16);
        cp16(sb + bbase + doff, g_whT + gsrc);
    }
}

__global__ void __launch_bounds__(256, 2) k_gemm_mma(const float* __restrict__ x) {
    extern __shared__ char smem[];
    const uint32_t sb = smem_u32(smem);
    const int tid = threadIdx.x, wid = tid >> 5, lane = tid & 31;
    const int row0 = blockIdx.x * A_ROWS;

    load_B_async(sb, 0, tid);
    CP_COMMIT();

    float* sbias = (float*)(smem + SM_BIAS);
    for (int i = tid; i < WC; i += 256) sbias[i] = g_bias[i];

    // load A tile [128x128] as fp16
    for (int i = tid; i < A_ROWS * 32; i += 256) {
        int r = i >> 5, k4 = (i & 31) << 2;
        int row = row0 + r;
        float4 v = (row < NN) ? __ldcs((const float4*)(x + (size_t)row * 128 + k4))
                              : make_float4(0.f, 0.f, 0.f, 0.f);
        __half2 h01 = __floats2half2_rn(v.x, v.y);
        __half2 h23 = __floats2half2_rn(v.z, v.w);
        uint32_t off = (uint32_t)(r * (A_STRIDE * 2) + k4 * 2);
        *(uint2*)(smem + SM_A + off) = make_uint2(*(uint32_t*)&h01, *(uint32_t*)&h23);
    }

    const int wm = wid & 3, wn = wid >> 2;       // warp grid 4 x 2
    const int rw = wm * 32, cw = wn * 64;        // warp tile 32 x 64
    const uint32_t a_off = (uint32_t)((rw + (lane & 15)) * (A_STRIDE * 2) + (lane >> 4) * 16);
    const uint32_t b_off = (uint32_t)((cw + (lane & 15)) * (B_STRIDE * 2) + (lane >> 4) * 16);
    const int trow = lane >> 2;
    const int tcol = (lane & 3) * 2;

    float acc[2][8][4];

    for (int s = 0; s < 12; ++s) {
        const int chunk = s >> 1, kh = s & 1;
        if (kh == 0) {
            #pragma unroll
            for (int i = 0; i < 2; ++i)
                #pragma unroll
                for (int j = 0; j < 8; ++j)
                    #pragma unroll
                    for (int q = 0; q < 4; ++q) acc[i][j][q] = 0.0f;
        }
        if (s + 1 < 12) {
            load_B_async(sb, s + 1, tid);
            CP_COMMIT();
            CP_WAIT1();
        } else {
            CP_WAIT0();
        }
        __syncthreads();

        const uint32_t sA = sb + SM_A + kh * 128;
        const uint32_t sBh = sb + SM_B + (uint32_t)(s & 1) * SZ_B;
        #pragma unroll
        for (int ks = 0; ks < 4; ++ks) {
            uint32_t a[2][4], bh[4][4];
            #pragma unroll
            for (int i = 0; i < 2; ++i)
                ldsm4(a[i], sA + a_off + i * (16 * A_STRIDE * 2) + ks * 32);
            #pragma unroll
            for (int j16 = 0; j16 < 4; ++j16)
                ldsm4(bh[j16], sBh + b_off + j16 * (16 * B_STRIDE * 2) + ks * 32);
            #pragma unroll
            for (int i = 0; i < 2; ++i) {
                #pragma unroll
                for (int j16 = 0; j16 < 4; ++j16) {
                    mma16816(acc[i][j16 * 2 + 0], a[i], bh[j16][0], bh[j16][2]);
                    mma16816(acc[i][j16 * 2 + 1], a[i], bh[j16][1], bh[j16][3]);
                }
            }
        }
        __syncthreads();

        if (kh == 1) {
            // route: q->g_dst[0..128), k/v->g_src, skip->g_dst[320..448),
            //        p->g_dst[128..320). All fp16.
            __half* bp; int stride, sub;
            if (chunk == 0)                 { bp = g_dst; stride = 448; sub = 0;   }
            else if (chunk == 1 || chunk == 2) { bp = g_src; stride = 256; sub = 128; }
            else if (chunk == 3)            { bp = g_dst; stride = 448; sub = 64;  }
            else                            { bp = g_dst; stride = 448; sub = 384; }
            #pragma unroll
            for (int i = 0; i < 2; ++i) {
                int r = row0 + rw + i * 16 + trow;
                #pragma unroll
                for (int j = 0; j < 8; ++j) {
                    int G = chunk * 128 + cw + j * 8 + tcol;
                    if (G >= 704) continue;
                    float b0 = sbias[G], b1 = sbias[G + 1];
                    if (r < NN) {
                        __half2 hv = __floats2half2_rn(acc[i][j][0] + b0,
                                                       acc[i][j][1] + b1);
                        *(__half2*)(bp + (size_t)r * stride + (G - sub)) = hv;
                    }
                    if (r + 8 < NN) {
                        __half2 hv = __floats2half2_rn(acc[i][j][2] + b0,
                                                       acc[i][j][3] + b1);
                        *(__half2*)(bp + (size_t)(r + 8) * stride + (G - sub)) = hv;
                    }
                }
            }
        }
    }
}

// ------------------------- sort: histogram, scan, permute -------------------------
__global__ void k_hist(const int* __restrict__ ei) {
    int i = blockIdx.x * blockDim.x + threadIdx.x;
    if (i < EE) atomicAdd(&g_cnt[__ldcs(ei + EE + i)], 1);
}

__global__ void k_scan_a() {
    __shared__ int sm[256];
    int t = threadIdx.x;
    int gid = blockIdx.x * 256 + t;
    int val = (gid < NN) ? g_cnt[gid] : 0;
    sm[t] = val;
    __syncthreads();
    #pragma unroll
    for (int o = 1; o < 256; o <<= 1) {
        int add = (t >= o) ? sm[t - o] : 0;
        __syncthreads();
        sm[t] += add;
        __syncthreads();
    }
    if (gid < NN) g_off[gid] = sm[t] - val;
    if (t == 255) g_bsum[blockIdx.x] = sm[255];
}

__global__ void k_scan_b(int nblk) {
    __shared__ int sm[512];
    int t = threadIdx.x;
    int val = (t < nblk) ? g_bsum[t] : 0;
    sm[t] = val;
    __syncthreads();
    #pragma unroll
    for (int o = 1; o < 512; o <<= 1) {
        int add = (t >= o) ? sm[t - o] : 0;
        __syncthreads();
        sm[t] += add;
        __syncthreads();
    }
    if (t < nblk) g_bsum[t] = sm[t] - val;
}

__global__ void k_scan_c() {
    int gid = blockIdx.x * 256 + threadIdx.x;
    if (gid < NN) g_off[gid] += g_bsum[blockIdx.x];
    if (gid == 0) g_off[NN] = EE;
}

__global__ void k_permute(const int* __restrict__ ei, const float* __restrict__ lu,
                          const float* __restrict__ tv) {
    int i = blockIdx.x * blockDim.x + threadIdx.x;
    if (i >= EE) return;
    int d = __ldcs(ei + EE + i);
    int s = __ldcs(ei + i);
    int pos = g_off[d] + atomicAdd(&g_cursor[d], 1);
    g_esrc[pos] = s;
    g_eidx[pos] = i;
    g_erel[pos] = lu[s] - __ldcs(tv + i);
}

// ------------------------- kernel: fused edge pass + s@We epilogue -------------
// Persistent single-wave grid (148*4 CTAs, 32 warps/SM). We in smem fp16.
// out is write-only: skip comes from g_dst fp16.
#define EDGE_CTAS 592
#define EDGE_WARPS (EDGE_CTAS * 8)
#define SM_WE_H (96 * 128 * 2)                  // 24576 B fp16 We
#define SM_EDGE (SM_WE_H + 8 * 192 * 4)         // + per-warp s fp32: 30720 B

__global__ void __launch_bounds__(256, 4) k_edge(const float* __restrict__ msg,
                                                 const float* __restrict__ time_w,
                                                 const float* __restrict__ time_b,
                                                 const float* __restrict__ We,
                                                 float* __restrict__ out) {
    extern __shared__ float sme[];
    __half* sWe = (__half*)sme;               // [96][128] fp16
    const int tid = threadIdx.x, wid = tid >> 5, lane = tid & 31;

    for (int i = tid; i < 96 * 128 / 4; i += 256) {
        float4 w = ((const float4*)We)[i];
        __half2 a = __floats2half2_rn(w.x, w.y);
        __half2 b = __floats2half2_rn(w.z, w.w);
        ((uint2*)sWe)[i] = make_uint2(*(uint32_t*)&a, *(uint32_t*)&b);
    }
    __syncthreads();

    float* sS = (float*)((char*)sme + SM_WE_H) + wid * 192;   // per-warp s[d][h]
    const float tww = time_w[lane], tbb = time_b[lane];
    const bool h0lane = (lane < 16);
    const int hsel = h0lane ? 0 : 1;

    for (int n = blockIdx.x * 8 + wid; n < NN; n += EDGE_WARPS) {
        const int off0 = g_off[n];
        const int deg = g_off[n + 1] - off0;
        const __half* dp = g_dst + (size_t)n * 448;

        if (deg == 0) {
            // out = skip only
            uint2 sk = __ldcs((const uint2*)(dp + 320 + lane * 4));
            float2 sa = __half22float2(*(const __half2*)&sk.x);
            float2 sbv = __half22float2(*(const __half2*)&sk.y);
            __stcs((float4*)(out + (size_t)n * 128 + lane * 4),
                   make_float4(sa.x, sa.y, sbv.x, sbv.y));
            continue;
        }

        uint2 qr = __ldcs((const uint2*)(dp + lane * 4));
        const __half2 qh01 = *(const __half2*)&qr.x;
        const __half2 qh23 = *(const __half2*)&qr.y;
        short ps0 = __ldcs((const short*)(dp + 128 + lane));
        short ps1 = __ldcs((const short*)(dp + 160 + lane));
        short ps2 = __ldcs((const short*)(dp + 192 + lane));
        short ps3 = __ldcs((const short*)(dp + 224 + lane));
        short ps4 = __ldcs((const short*)(dp + 256 + lane));
        short ps5 = __ldcs((const short*)(dp + 288 + lane));
        const float p00 = __half2float(*(__half*)&ps0), p01 = __half2float(*(__half*)&ps1);
        const float p02 = __half2float(*(__half*)&ps2), p10 = __half2float(*(__half*)&ps3);
        const float p11 = __half2float(*(__half*)&ps4), p12 = __half2float(*(__half*)&ps5);

        float den0 = 0.f, den1 = 0.f;
        float4 aco = make_float4(0.f, 0.f, 0.f, 0.f);
        float2 as0 = make_float2(0.f, 0.f), as1 = as0, as2 = as0;

        for (int eb = 0; eb < deg; eb += 4) {
            const int nb = deg - eb;
            int idxj[4];
            float relj[4], ea0[4], ea1[4], ea2[4], u0[4], u1[4];
            uint2 kr[4], vr[4];
            #pragma unroll
            for (int j = 0; j < 4; ++j) {
                int pos = off0 + eb + ((j < nb) ? j : 0);
                int src = __ldcs(g_esrc + pos);
                idxj[j] = __ldcs(g_eidx + pos);
                relj[j] = __ldcs(g_erel + pos);
                const __half* sp = g_src + (size_t)src * 256;
                kr[j] = *(const uint2*)(sp + lane * 4);        // cached: reused ~8x
                vr[j] = *(const uint2*)(sp + 128 + lane * 4);
            }
            #pragma unroll
            for (int j = 0; j < 4; ++j) {
                ea1[j] = __ldcs(msg + (size_t)idxj[j] * 64 + lane);
                ea2[j] = __ldcs(msg + (size_t)idxj[j] * 64 + 32 + lane);
            }
            #pragma unroll
            for (int j = 0; j < 4; ++j) {
                __half2 t = __hmul2(qh01, *(const __half2*)&kr[j].x);
                t = __hfma2(qh23, *(const __half2*)&kr[j].y, t);
                float2 tf = __half22float2(t);
                float qk = tf.x + tf.y;
                ea0[j] = cosf(fmaf(relj[j], tww, tbb));
                u0[j] = ea0[j] * p00 + ea1[j] * p01 + ea2[j] * p02 + (h0lane ? qk : 0.f);
                u1[j] = ea0[j] * p10 + ea1[j] * p11 + ea2[j] * p12 + (h0lane ? 0.f : qk);
            }
            // joint reduction: fold heads after one xor-16 step.
            float w[4], oth[4];
            #pragma unroll
            for (int j = 0; j < 4; ++j) {
                u0[j] += __shfl_xor_sync(0xffffffffu, u0[j], 16);
                u1[j] += __shfl_xor_sync(0xffffffffu, u1[j], 16);
                w[j] = h0lane ? u0[j] : u1[j];
            }
            #pragma unroll
            for (int o = 8; o; o >>= 1) {
                #pragma unroll
                for (int j = 0; j < 4; ++j)
                    w[j] += __shfl_xor_sync(0xffffffffu, w[j], o);
            }
            #pragma unroll
            for (int j = 0; j < 4; ++j)
                oth[j] = __shfl_xor_sync(0xffffffffu, w[j], 16);

            #pragma unroll
            for (int j = 0; j < 4; ++j) {
                if (j < nb) {
                    float eo = __expf(w[j] * 0.125f);
                    float ex = __expf(oth[j] * 0.125f);
                    float e0 = h0lane ? eo : ex;
                    float e1 = h0lane ? ex : eo;
                    den0 += e0; den1 += e1;
                    float2 va = __half22float2(*(const __half2*)&vr[j].x);
                    float2 vb = __half22float2(*(const __half2*)&vr[j].y);
                    aco.x = fmaf(va.x, eo, aco.x);
                    aco.y = fmaf(va.y, eo, aco.y);
                    aco.z = fmaf(vb.x, eo, aco.z);
                    aco.w = fmaf(vb.y, eo, aco.w);
                    as0.x = fmaf(ea0[j], e0, as0.x);  as0.y = fmaf(ea0[j], e1, as0.y);
                    as1.x = fmaf(ea1[j], e0, as1.x);  as1.y = fmaf(ea1[j], e1, as1.y);
                    as2.x = fmaf(ea2[j], e0, as2.x);  as2.y = fmaf(ea2[j], e1, as2.y);
                }
            }
        }

        float i0 = 1.0f / (den0 + 1e-16f);
        float i1 = 1.0f / (den1 + 1e-16f);

        // stage normalized s into per-warp smem: sS[d*2 + h]
        sS[lane * 2 + 0]        = as0.x * i0;  sS[lane * 2 + 1]        = as0.y * i1;
        sS[(lane + 32) * 2 + 0] = as1.x * i0;  sS[(lane + 32) * 2 + 1] = as1.y * i1;
        sS[(lane + 64) * 2 + 0] = as2.x * i0;  sS[(lane + 64) * 2 + 1] = as2.y * i1;
        __syncwarp();

        // matvec: r[c] = sum_d s[d][h(c)] * We[d][c], cols c = lane*4..lane*4+3
        unsigned long long a01 = 0ULL, a23 = 0ULL;
        const uint2* wh = (const uint2*)sWe + lane;   // 4 halves per lane per d
        #pragma unroll 8
        for (int d = 0; d < 96; ++d) {
            float sv = sS[d * 2 + hsel];
            uint2 hw = wh[d * 32];
            float2 w01 = __half22float2(*(const __half2*)&hw.x);
            float2 w23 = __half22float2(*(const __half2*)&hw.y);
            unsigned long long svp = pk2(sv, sv);
            a01 = ffma2(pk2(w01.x, w01.y), svp, a01);
            a23 = ffma2(pk2(w23.x, w23.y), svp, a23);
        }
        __syncwarp();
        float2 r01 = upk2(a01), r23 = upk2(a23);

        // skip from g_dst fp16; out written once (no RMW)
        uint2 sk = __ldcs((const uint2*)(dp + 320 + lane * 4));
        float2 sa = __half22float2(*(const __half2*)&sk.x);
        float2 sbv = __half22float2(*(const __half2*)&sk.y);

        float ih = h0lane ? i0 : i1;
        float4 o4;
        o4.x = sa.x  + aco.x * ih + r01.x;
        o4.y = sa.y  + aco.y * ih + r01.y;
        o4.z = sbv.x + aco.z * ih + r23.x;
        o4.w = sbv.y + aco.w * ih + r23.y;
        __stcs((float4*)(out + (size_t)n * 128 + lane * 4), o4);
    }
}

// ------------------------- launch -------------------------
extern "C" void kernel_launch(void* const* d_in, const int* in_sizes, int n_in,
                              void* d_out, int out_size) {
    const float* x   = (const float*)d_in[0];
    const float* lu  = (const float*)d_in[1];
    const float* tv  = (const float*)d_in[2];
    const float* msg = (const float*)d_in[3];
    const int*   ei  = (const int*)d_in[4];
    const float* tw  = (const float*)d_in[5];
    const float* tb  = (const float*)d_in[6];
    const float* Wq  = (const float*)d_in[7];
    const float* bq  = (const float*)d_in[8];
    const float* Wk  = (const float*)d_in[9];
    const float* bk  = (const float*)d_in[10];
    const float* Wv  = (const float*)d_in[11];
    const float* bv  = (const float*)d_in[12];
    const float* We  = (const float*)d_in[13];
    const float* Ws  = (const float*)d_in[14];
    const float* bs  = (const float*)d_in[15];
    float* out = (float*)d_out;

    static cudaStream_t s2 = nullptr;
    static cudaEvent_t evFork = nullptr, evJoin = nullptr;
    if (!s2) {
        cudaFuncSetAttribute(k_gemm_mma, cudaFuncAttributeMaxDynamicSharedMemorySize, SM_TOT);
        cudaFuncSetAttribute(k_edge, cudaFuncAttributeMaxDynamicSharedMemorySize, SM_EDGE);
        cudaStreamCreateWithFlags(&s2, cudaStreamNonBlocking);
        cudaEventCreateWithFlags(&evFork, cudaEventDisableTiming);
        cudaEventCreateWithFlags(&evJoin, cudaEventDisableTiming);
    }

    const int nblk = (NN + 255) / 256;  // 391

    // Fork s2 off the main stream.
    cudaEventRecord(evFork, 0);
    cudaStreamWaitEvent(s2, evFork, 0);

    // Submission order chosen so index 3 = k_gemm_mma (ncu profiles idx 3).
    k_prep<<<128, 256>>>(Wq, bq, Wk, bk, Wv, bv, We, Ws, bs);         // idx 0 (main)
    k_init<<<nblk, 256, 0, s2>>>();                                   // idx 1 (s2)
    k_hist<<<(EE + 255) / 256, 256, 0, s2>>>(ei);                     // idx 2 (s2)
    k_gemm_mma<<<(NN + A_ROWS - 1) / A_ROWS, 256, SM_TOT>>>(x);       // idx 3 (main)
    k_scan_a<<<nblk, 256, 0, s2>>>();                                 // idx 4
    k_scan_b<<<1, 512, 0, s2>>>(nblk);                                // idx 5
    k_scan_c<<<nblk, 256, 0, s2>>>();                                 // idx 6
    k_permute<<<(EE + 255) / 256, 256, 0, s2>>>(ei, lu, tv);          // idx 7
    cudaEventRecord(evJoin, s2);

    // Join, then fused edge pass (attn + skip + s@We epilogue; writes out once).
    cudaStreamWaitEvent(0, evJoin, 0);
    k_edge<<<EDGE_CTAS, 256, SM_EDGE>>>(msg, tw, tb, We, out);        // idx 8
}